// round 6
// baseline (speedup 1.0000x reference)
#include <cuda_runtime.h>
#include <cuda_bf16.h>
#include <cstdint>
#include <cstddef>

// Problem constants
#define NN   100000
#define EE   3200000
#define FF   256        // NFEAT == NHID
#define NOUT 128

// ---------------------------------------------------------------------------
// Scratch (static __device__ globals; no allocation anywhere)
// ---------------------------------------------------------------------------
__device__ int   g_cursor[NN];
__device__ int   g_rowptr[NN + 1];
__device__ int   g_cols[EE];
__device__ float g_vals[EE];
__device__ float g_self[(size_t)NN * FF];      // x @ W_self
__device__ float g_support[(size_t)NN * FF];   // x @ W_nb
__device__ float g_x[(size_t)NN * FF];         // layer-1 output
__device__ float g_l1[NN], g_l2[NN];
__device__ float g_r[NN], g_z[NN];
__device__ float g_red[4];                     // m1, m2, s1, s2
__device__ float g_colsum[FF];

// ---------------------------------------------------------------------------
// CSR construction
// ---------------------------------------------------------------------------
__global__ void zero_kernel(int* cursor, float* colsum, float* red, int n)
{
    int i = blockIdx.x * blockDim.x + threadIdx.x;
    if (i < n)   cursor[i] = 0;
    if (i < FF)  colsum[i] = 0.f;
    if (i < 4)   red[i] = 0.f;
}

__global__ void hist_kernel(const int* __restrict__ edge_row, int* __restrict__ cnt, int e)
{
    int i = blockIdx.x * blockDim.x + threadIdx.x;
    if (i < e) atomicAdd(&cnt[edge_row[i]], 1);
}

// single-block exclusive scan over NN counts -> rowptr[NN+1]
__global__ void scan_kernel(const int* __restrict__ cnt, int* __restrict__ rowptr, int n)
{
    __shared__ int warpsums[32];
    __shared__ int carry_s;
    int tid = threadIdx.x;
    int lane = tid & 31, w = tid >> 5;
    if (tid == 0) carry_s = 0;
    __syncthreads();
    for (int base = 0; base < n; base += 1024) {
        int i = base + tid;
        int v = (i < n) ? cnt[i] : 0;
        int incl = v;
        #pragma unroll
        for (int o = 1; o < 32; o <<= 1) {
            int t = __shfl_up_sync(0xFFFFFFFFu, incl, o);
            if (lane >= o) incl += t;
        }
        if (lane == 31) warpsums[w] = incl;
        __syncthreads();
        if (w == 0) {
            int s = warpsums[lane];
            #pragma unroll
            for (int o = 1; o < 32; o <<= 1) {
                int t = __shfl_up_sync(0xFFFFFFFFu, s, o);
                if (lane >= o) s += t;
            }
            warpsums[lane] = s;
        }
        __syncthreads();
        int blockIncl = incl + (w > 0 ? warpsums[w - 1] : 0);
        int carry = carry_s;
        if (i < n) rowptr[i] = carry + blockIncl - v;   // exclusive
        __syncthreads();
        if (tid == 1023) carry_s = carry + blockIncl;   // add block total
        __syncthreads();
    }
    if (tid == 0) rowptr[n] = carry_s;
}

__global__ void copy_cursor_kernel(const int* __restrict__ rowptr, int* __restrict__ cursor, int n)
{
    int i = blockIdx.x * blockDim.x + threadIdx.x;
    if (i < n) cursor[i] = rowptr[i];
}

__global__ void scatter_kernel(const int* __restrict__ edge_row,
                               const int* __restrict__ edge_col,
                               const float* __restrict__ edge_val,
                               int* __restrict__ cursor,
                               int* __restrict__ cols, float* __restrict__ vals, int e)
{
    int i = blockIdx.x * blockDim.x + threadIdx.x;
    if (i < e) {
        int r = edge_row[i];
        int p = atomicAdd(&cursor[r], 1);
        cols[p] = edge_col[i];
        vals[p] = edge_val[i];
    }
}

// ---------------------------------------------------------------------------
// SGEMM: C[M,256] = diag(rowScale) * A[M,256] @ B[256,256]
// 128x128x16 tile, 256 threads, 8x8 micro-tile
// ---------------------------------------------------------------------------
__global__ void __launch_bounds__(256)
sgemm_kernel(const float* __restrict__ A, const float* __restrict__ B,
             float* __restrict__ C, int M, const float* __restrict__ rowScale)
{
    __shared__ float As[16][128];   // [k][row]
    __shared__ float Bs[16][128];   // [k][col]

    int tid = threadIdx.x;
    int rowTile = blockIdx.x * 128;
    int colTile = blockIdx.y * 128;
    int ty = tid >> 4, tx = tid & 15;

    float acc[8][8];
    #pragma unroll
    for (int i = 0; i < 8; i++)
        #pragma unroll
        for (int j = 0; j < 8; j++) acc[i][j] = 0.f;

    for (int k0 = 0; k0 < 256; k0 += 16) {
        // load A tile: 128 rows x 16 k = 512 float4 (4 float4 per row)
        #pragma unroll
        for (int i = 0; i < 2; i++) {
            int f  = tid + i * 256;
            int r  = f >> 2;        // row within tile
            int kq = f & 3;         // which float4 in the row
            int grow = rowTile + r;
            float4 v = make_float4(0.f, 0.f, 0.f, 0.f);
            if (grow < M) {
                v = *(const float4*)(A + (size_t)grow * 256 + k0 + kq * 4);
                if (rowScale) {
                    float s = rowScale[grow];
                    v.x *= s; v.y *= s; v.z *= s; v.w *= s;
                }
            }
            As[kq * 4 + 0][r] = v.x;
            As[kq * 4 + 1][r] = v.y;
            As[kq * 4 + 2][r] = v.z;
            As[kq * 4 + 3][r] = v.w;
        }
        // load B tile: 16 k-rows x 128 cols = 512 float4
        #pragma unroll
        for (int i = 0; i < 2; i++) {
            int f  = tid + i * 256;
            int kr = f >> 5;        // 0..15
            int cq = f & 31;        // 0..31
            float4 v = *(const float4*)(B + (size_t)(k0 + kr) * 256 + colTile + cq * 4);
            *(float4*)&Bs[kr][cq * 4] = v;
        }
        __syncthreads();
        #pragma unroll
        for (int k = 0; k < 16; k++) {
            float4 a0 = *(float4*)&As[k][ty * 8];
            float4 a1 = *(float4*)&As[k][ty * 8 + 4];
            float4 b0 = *(float4*)&Bs[k][tx * 8];
            float4 b1 = *(float4*)&Bs[k][tx * 8 + 4];
            float a[8] = {a0.x, a0.y, a0.z, a0.w, a1.x, a1.y, a1.z, a1.w};
            float b[8] = {b0.x, b0.y, b0.z, b0.w, b1.x, b1.y, b1.z, b1.w};
            #pragma unroll
            for (int i = 0; i < 8; i++)
                #pragma unroll
                for (int j = 0; j < 8; j++)
                    acc[i][j] = fmaf(a[i], b[j], acc[i][j]);
        }
        __syncthreads();
    }

    #pragma unroll
    for (int i = 0; i < 8; i++) {
        int grow = rowTile + ty * 8 + i;
        if (grow < M) {
            #pragma unroll
            for (int j = 0; j < 8; j += 4) {
                float4 v = make_float4(acc[i][j], acc[i][j+1], acc[i][j+2], acc[i][j+3]);
                *(float4*)(C + (size_t)grow * 256 + colTile + tx * 8 + j) = v;
            }
        }
    }
}

// ---------------------------------------------------------------------------
// Aggregation: out[i] = relu(self[i] + sum_{edges of i} val * support[col] + b)
// One block per row, thread j owns column j.
// ---------------------------------------------------------------------------
__global__ void __launch_bounds__(256)
agg1_kernel(const float* __restrict__ selfbuf, const float* __restrict__ support,
            const int* __restrict__ rowptr, const int* __restrict__ cols,
            const float* __restrict__ vals, const float* __restrict__ bias,
            float* __restrict__ out)
{
    int i = blockIdx.x;
    int j = threadIdx.x;
    __shared__ int   sc[128];
    __shared__ float sv[128];
    int s = rowptr[i], e = rowptr[i + 1];
    float acc = selfbuf[(size_t)i * FF + j];
    for (int b0 = s; b0 < e; b0 += 128) {
        int n = min(128, e - b0);
        __syncthreads();
        if (j < n) { sc[j] = cols[b0 + j]; sv[j] = vals[b0 + j]; }
        __syncthreads();
        #pragma unroll 4
        for (int t = 0; t < n; t++)
            acc = fmaf(sv[t], support[(size_t)sc[t] * FF + j], acc);
    }
    out[(size_t)i * FF + j] = fmaxf(acc + bias[j], 0.f);
}

// Layer 2 variant: fused gated combine, writes x_enc directly to d_out
__global__ void __launch_bounds__(256)
agg2_kernel(const float* __restrict__ selfbuf, const float* __restrict__ support,
            const int* __restrict__ rowptr, const int* __restrict__ cols,
            const float* __restrict__ vals, const float* __restrict__ bias,
            const float* __restrict__ x, const float* __restrict__ z,
            float* __restrict__ xenc)
{
    int i = blockIdx.x;
    int j = threadIdx.x;
    __shared__ int   sc[128];
    __shared__ float sv[128];
    int s = rowptr[i], e = rowptr[i + 1];
    float acc = selfbuf[(size_t)i * FF + j];
    for (int b0 = s; b0 < e; b0 += 128) {
        int n = min(128, e - b0);
        __syncthreads();
        if (j < n) { sc[j] = cols[b0 + j]; sv[j] = vals[b0 + j]; }
        __syncthreads();
        #pragma unroll 4
        for (int t = 0; t < n; t++)
            acc = fmaf(sv[t], support[(size_t)sc[t] * FF + j], acc);
    }
    float x2 = fmaxf(acc + bias[j], 0.f);
    float zi = z[i];
    xenc[(size_t)i * FF + j] = (1.f - zi) * x[(size_t)i * FF + j] + zi * x2;
}

// ---------------------------------------------------------------------------
// Gates: logits, softmax over nodes, r/z
// ---------------------------------------------------------------------------
__global__ void gate_logits_kernel(const float* __restrict__ x,
                                   const float* __restrict__ w1, const float* __restrict__ b1,
                                   const float* __restrict__ w2, const float* __restrict__ b2,
                                   float* __restrict__ l1, float* __restrict__ l2, int n)
{
    int warp = (blockIdx.x * blockDim.x + threadIdx.x) >> 5;
    int lane = threadIdx.x & 31;
    if (warp >= n) return;
    const float* xr = x + (size_t)warp * FF;
    float s1 = 0.f, s2 = 0.f;
    #pragma unroll
    for (int q = 0; q < 8; q++) {
        int k = lane + q * 32;
        float xv = xr[k];
        s1 = fmaf(xv, w1[k], s1);
        s2 = fmaf(xv, w2[k], s2);
    }
    #pragma unroll
    for (int o = 16; o > 0; o >>= 1) {
        s1 += __shfl_down_sync(0xFFFFFFFFu, s1, o);
        s2 += __shfl_down_sync(0xFFFFFFFFu, s2, o);
    }
    if (lane == 0) { l1[warp] = s1 + b1[0]; l2[warp] = s2 + b2[0]; }
}

__global__ void reduce_max_kernel(const float* __restrict__ l1, const float* __restrict__ l2,
                                  float* __restrict__ red, int n)
{
    float m1 = -3.4e38f, m2 = -3.4e38f;
    for (int i = threadIdx.x; i < n; i += blockDim.x) {
        m1 = fmaxf(m1, l1[i]); m2 = fmaxf(m2, l2[i]);
    }
    __shared__ float sh1[32], sh2[32];
    int lane = threadIdx.x & 31, w = threadIdx.x >> 5;
    #pragma unroll
    for (int o = 16; o > 0; o >>= 1) {
        m1 = fmaxf(m1, __shfl_xor_sync(0xFFFFFFFFu, m1, o));
        m2 = fmaxf(m2, __shfl_xor_sync(0xFFFFFFFFu, m2, o));
    }
    if (lane == 0) { sh1[w] = m1; sh2[w] = m2; }
    __syncthreads();
    if (w == 0) {
        m1 = (lane < (int)(blockDim.x >> 5)) ? sh1[lane] : -3.4e38f;
        m2 = (lane < (int)(blockDim.x >> 5)) ? sh2[lane] : -3.4e38f;
        #pragma unroll
        for (int o = 16; o > 0; o >>= 1) {
            m1 = fmaxf(m1, __shfl_xor_sync(0xFFFFFFFFu, m1, o));
            m2 = fmaxf(m2, __shfl_xor_sync(0xFFFFFFFFu, m2, o));
        }
        if (lane == 0) { red[0] = m1; red[1] = m2; }
    }
}

__global__ void reduce_sumexp_kernel(const float* __restrict__ l1, const float* __restrict__ l2,
                                     float* __restrict__ red, int n)
{
    float m1 = red[0], m2 = red[1];
    float s1 = 0.f, s2 = 0.f;
    for (int i = threadIdx.x; i < n; i += blockDim.x) {
        s1 += expf(l1[i] - m1);
        s2 += expf(l2[i] - m2);
    }
    __shared__ float sh1[32], sh2[32];
    int lane = threadIdx.x & 31, w = threadIdx.x >> 5;
    #pragma unroll
    for (int o = 16; o > 0; o >>= 1) {
        s1 += __shfl_xor_sync(0xFFFFFFFFu, s1, o);
        s2 += __shfl_xor_sync(0xFFFFFFFFu, s2, o);
    }
    if (lane == 0) { sh1[w] = s1; sh2[w] = s2; }
    __syncthreads();
    if (w == 0) {
        s1 = (lane < (int)(blockDim.x >> 5)) ? sh1[lane] : 0.f;
        s2 = (lane < (int)(blockDim.x >> 5)) ? sh2[lane] : 0.f;
        #pragma unroll
        for (int o = 16; o > 0; o >>= 1) {
            s1 += __shfl_xor_sync(0xFFFFFFFFu, s1, o);
            s2 += __shfl_xor_sync(0xFFFFFFFFu, s2, o);
        }
        if (lane == 0) { red[2] = s1; red[3] = s2; }
    }
}

__global__ void rz_kernel(const float* __restrict__ l1, const float* __restrict__ l2,
                          const float* __restrict__ red,
                          float* __restrict__ r, float* __restrict__ z, int n)
{
    int i = blockIdx.x * blockDim.x + threadIdx.x;
    if (i < n) {
        r[i] = expf(l1[i] - red[0]) / red[2];
        z[i] = expf(l2[i] - red[1]) / red[3];
    }
}

// ---------------------------------------------------------------------------
// Mean over nodes + final projection
// ---------------------------------------------------------------------------
__global__ void colsum_kernel(const float* __restrict__ xenc, float* __restrict__ colacc, int n)
{
    int j = threadIdx.x;             // 256 columns
    int r0 = blockIdx.x * 64;
    int r1 = min(r0 + 64, n);
    float s = 0.f;
    for (int r = r0; r < r1; r++) s += xenc[(size_t)r * FF + j];
    atomicAdd(&colacc[j], s);
}

__global__ void final_kernel(const float* __restrict__ colacc,
                             const float* __restrict__ e2p_w, const float* __restrict__ e2p_b,
                             float* __restrict__ out)
{
    int o = threadIdx.x;             // 128 outputs
    float s = 0.f;
    #pragma unroll 8
    for (int k = 0; k < FF; k++)
        s = fmaf(colacc[k] * (1.0f / (float)NN), e2p_w[(size_t)k * NOUT + o], s);
    out[o] = s + e2p_b[o];
}

// ---------------------------------------------------------------------------
// Launch
// ---------------------------------------------------------------------------
extern "C" void kernel_launch(void* const* d_in, const int* in_sizes, int n_in,
                              void* d_out, int out_size)
{
    const float* inputs   = (const float*)d_in[0];
    const int*   edge_row = (const int*)  d_in[1];
    const int*   edge_col = (const int*)  d_in[2];
    const float* edge_val = (const float*)d_in[3];
    const float* W_self1  = (const float*)d_in[4];
    const float* W_nb1    = (const float*)d_in[5];
    const float* b1       = (const float*)d_in[6];
    const float* W_self2  = (const float*)d_in[7];
    const float* W_nb2    = (const float*)d_in[8];
    const float* b2       = (const float*)d_in[9];
    const float* gate1_w  = (const float*)d_in[10];
    const float* gate1_b  = (const float*)d_in[11];
    const float* gate2_w  = (const float*)d_in[12];
    const float* gate2_b  = (const float*)d_in[13];
    const float* e2p_w    = (const float*)d_in[14];
    const float* e2p_b    = (const float*)d_in[15];

    float* xenc = (float*)d_out;                       // [NN, FF]
    float* out  = (float*)d_out + (size_t)NN * FF;     // [NOUT]

    int*   p_cursor;  cudaGetSymbolAddress((void**)&p_cursor,  g_cursor);
    int*   p_rowptr;  cudaGetSymbolAddress((void**)&p_rowptr,  g_rowptr);
    int*   p_cols;    cudaGetSymbolAddress((void**)&p_cols,    g_cols);
    float* p_vals;    cudaGetSymbolAddress((void**)&p_vals,    g_vals);
    float* p_self;    cudaGetSymbolAddress((void**)&p_self,    g_self);
    float* p_support; cudaGetSymbolAddress((void**)&p_support, g_support);
    float* p_x;       cudaGetSymbolAddress((void**)&p_x,       g_x);
    float* p_l1;      cudaGetSymbolAddress((void**)&p_l1,      g_l1);
    float* p_l2;      cudaGetSymbolAddress((void**)&p_l2,      g_l2);
    float* p_r;       cudaGetSymbolAddress((void**)&p_r,       g_r);
    float* p_z;       cudaGetSymbolAddress((void**)&p_z,       g_z);
    float* p_red;     cudaGetSymbolAddress((void**)&p_red,     g_red);
    float* p_colsum;  cudaGetSymbolAddress((void**)&p_colsum,  g_colsum);

    const int TB = 256;
    dim3 gemmGrid((NN + 127) / 128, 2);

    // CSR build
    zero_kernel<<<(NN + TB - 1) / TB, TB>>>(p_cursor, p_colsum, p_red, NN);
    hist_kernel<<<(EE + TB - 1) / TB, TB>>>(edge_row, p_cursor, EE);
    scan_kernel<<<1, 1024>>>(p_cursor, p_rowptr, NN);
    copy_cursor_kernel<<<(NN + TB - 1) / TB, TB>>>(p_rowptr, p_cursor, NN);
    scatter_kernel<<<(EE + TB - 1) / TB, TB>>>(edge_row, edge_col, edge_val,
                                               p_cursor, p_cols, p_vals, EE);

    // Layer 1
    sgemm_kernel<<<gemmGrid, TB>>>(inputs, W_self1, p_self,    NN, nullptr);
    sgemm_kernel<<<gemmGrid, TB>>>(inputs, W_nb1,   p_support, NN, nullptr);
    agg1_kernel<<<NN, TB>>>(p_self, p_support, p_rowptr, p_cols, p_vals, b1, p_x);

    // Gates: r = softmax(x@g1w + g1b), z = softmax(x@g2w + g2b) over nodes
    gate_logits_kernel<<<(NN * 32 + TB - 1) / TB, TB>>>(p_x, gate1_w, gate1_b,
                                                        gate2_w, gate2_b, p_l1, p_l2, NN);
    reduce_max_kernel<<<1, 1024>>>(p_l1, p_l2, p_red, NN);
    reduce_sumexp_kernel<<<1, 1024>>>(p_l1, p_l2, p_red, NN);
    rz_kernel<<<(NN + TB - 1) / TB, TB>>>(p_l1, p_l2, p_red, p_r, p_z, NN);

    // Layer 2 (row-scale r fused into GEMM A-loads)
    sgemm_kernel<<<gemmGrid, TB>>>(p_x, W_self2, p_self,    NN, p_r);
    sgemm_kernel<<<gemmGrid, TB>>>(p_x, W_nb2,   p_support, NN, p_r);
    agg2_kernel<<<NN, TB>>>(p_self, p_support, p_rowptr, p_cols, p_vals, b2,
                            p_x, p_z, xenc);

    // mean over nodes -> e2p
    colsum_kernel<<<(NN + 63) / 64, TB>>>(xenc, p_colsum, NN);
    final_kernel<<<1, NOUT>>>(p_colsum, e2p_w, e2p_b, out);
}

// round 9
// speedup vs baseline: 1.9046x; 1.9046x over previous
#include <cuda_runtime.h>
#include <cuda_bf16.h>
#include <cstdint>
#include <cstddef>

// Problem constants
#define NN   100000
#define EE   3200000
#define FF   256        // NFEAT == NHID
#define NOUT 128
#define MPAD 100096     // 782 * 128

// ---------------------------------------------------------------------------
// Scratch (static __device__ globals; no allocation anywhere)
// ---------------------------------------------------------------------------
__device__ int   g_cursor[NN];
__device__ int   g_rowptr[NN + 1];
__device__ int   g_cols[EE];
__device__ float g_vals[EE];
__device__ float g_self[(size_t)NN * FF];      // x @ W_self
__device__ float g_support[(size_t)NN * FF];   // x @ W_nb
__device__ float g_x[(size_t)NN * FF];         // layer-1 output
__device__ float g_l1[NN], g_l2[NN];
__device__ float g_r[NN], g_z[NN];
__device__ float g_red[4];
__device__ float g_colsum[FF];
// bf16-split operands
__device__ __nv_bfloat16 g_Ahi[(size_t)MPAD * FF];
__device__ __nv_bfloat16 g_Alo[(size_t)MPAD * FF];
__device__ __nv_bfloat16 g_Bthi[2 * 512 * 256];   // [layer][n][k], n = [self | nb]
__device__ __nv_bfloat16 g_Btlo[2 * 512 * 256];

// ---------------------------------------------------------------------------
// mma.sync / ldmatrix helpers (baseline PTX, no sm_103a-only features)
// ---------------------------------------------------------------------------
__device__ __forceinline__ void ldsm4(uint32_t* r, uint32_t addr) {
    asm volatile("ldmatrix.sync.aligned.m8n8.x4.shared.b16 {%0,%1,%2,%3}, [%4];"
        : "=r"(r[0]), "=r"(r[1]), "=r"(r[2]), "=r"(r[3]) : "r"(addr));
}

__device__ __forceinline__ void mma16816(float* c, const uint32_t* a, const uint32_t* b) {
    asm volatile("mma.sync.aligned.m16n8k16.row.col.f32.bf16.bf16.f32 "
        "{%0,%1,%2,%3}, {%4,%5,%6,%7}, {%8,%9}, {%0,%1,%2,%3};"
        : "+f"(c[0]), "+f"(c[1]), "+f"(c[2]), "+f"(c[3])
        : "r"(a[0]), "r"(a[1]), "r"(a[2]), "r"(a[3]), "r"(b[0]), "r"(b[1]));
}

// ---------------------------------------------------------------------------
// CSR construction
// ---------------------------------------------------------------------------
__global__ void zero_kernel(int* cursor, float* colsum, float* red, int n)
{
    int i = blockIdx.x * blockDim.x + threadIdx.x;
    if (i < n)   cursor[i] = 0;
    if (i < FF)  colsum[i] = 0.f;
    if (i < 4)   red[i] = 0.f;
}

__global__ void hist_kernel(const int* __restrict__ edge_row, int* __restrict__ cnt, int e)
{
    int i = blockIdx.x * blockDim.x + threadIdx.x;
    if (i < e) atomicAdd(&cnt[edge_row[i]], 1);
}

__global__ void scan_kernel(const int* __restrict__ cnt, int* __restrict__ rowptr, int n)
{
    __shared__ int warpsums[32];
    __shared__ int carry_s;
    int tid = threadIdx.x;
    int lane = tid & 31, w = tid >> 5;
    if (tid == 0) carry_s = 0;
    __syncthreads();
    for (int base = 0; base < n; base += 1024) {
        int i = base + tid;
        int v = (i < n) ? cnt[i] : 0;
        int incl = v;
        #pragma unroll
        for (int o = 1; o < 32; o <<= 1) {
            int t = __shfl_up_sync(0xFFFFFFFFu, incl, o);
            if (lane >= o) incl += t;
        }
        if (lane == 31) warpsums[w] = incl;
        __syncthreads();
        if (w == 0) {
            int s = warpsums[lane];
            #pragma unroll
            for (int o = 1; o < 32; o <<= 1) {
                int t = __shfl_up_sync(0xFFFFFFFFu, s, o);
                if (lane >= o) s += t;
            }
            warpsums[lane] = s;
        }
        __syncthreads();
        int blockIncl = incl + (w > 0 ? warpsums[w - 1] : 0);
        int carry = carry_s;
        if (i < n) rowptr[i] = carry + blockIncl - v;
        __syncthreads();
        if (tid == 1023) carry_s = carry + blockIncl;
        __syncthreads();
    }
    if (tid == 0) rowptr[n] = carry_s;
}

__global__ void copy_cursor_kernel(const int* __restrict__ rowptr, int* __restrict__ cursor, int n)
{
    int i = blockIdx.x * blockDim.x + threadIdx.x;
    if (i < n) cursor[i] = rowptr[i];
}

__global__ void scatter_kernel(const int* __restrict__ edge_row,
                               const int* __restrict__ edge_col,
                               const float* __restrict__ edge_val,
                               int* __restrict__ cursor,
                               int* __restrict__ cols, float* __restrict__ vals, int e)
{
    int i = blockIdx.x * blockDim.x + threadIdx.x;
    if (i < e) {
        int r = edge_row[i];
        int p = atomicAdd(&cursor[r], 1);
        cols[p] = edge_col[i];
        vals[p] = edge_val[i];
    }
}

// ---------------------------------------------------------------------------
// bf16-split conversions
// ---------------------------------------------------------------------------
__global__ void convertA_kernel(const float* __restrict__ src, const float* __restrict__ rowScale,
                                __nv_bfloat16* __restrict__ hi, __nv_bfloat16* __restrict__ lo, int M)
{
    size_t idx = (size_t)blockIdx.x * 256 + threadIdx.x;   // one float4 group (4 elems)
    int row = (int)(idx >> 6);                             // 64 groups per 256-wide row
    if (row >= MPAD) return;
    float4 v = make_float4(0.f, 0.f, 0.f, 0.f);
    if (row < M) {
        v = *(const float4*)(src + idx * 4);
        if (rowScale) { float s = rowScale[row]; v.x *= s; v.y *= s; v.z *= s; v.w *= s; }
    }
    __nv_bfloat16 h0 = __float2bfloat16(v.x), h1 = __float2bfloat16(v.y);
    __nv_bfloat16 h2 = __float2bfloat16(v.z), h3 = __float2bfloat16(v.w);
    __nv_bfloat16 l0 = __float2bfloat16(v.x - __bfloat162float(h0));
    __nv_bfloat16 l1 = __float2bfloat16(v.y - __bfloat162float(h1));
    __nv_bfloat16 l2 = __float2bfloat16(v.z - __bfloat162float(h2));
    __nv_bfloat16 l3 = __float2bfloat16(v.w - __bfloat162float(h3));
    __nv_bfloat162* hp = (__nv_bfloat162*)(hi + idx * 4);
    __nv_bfloat162* lp = (__nv_bfloat162*)(lo + idx * 4);
    hp[0] = __halves2bfloat162(h0, h1); hp[1] = __halves2bfloat162(h2, h3);
    lp[0] = __halves2bfloat162(l0, l1); lp[1] = __halves2bfloat162(l2, l3);
}

// Transpose + split all 4 weight matrices into [layer][n 0..511][k] bf16 hi/lo
__global__ void convertB_kernel(const float* __restrict__ Ws1, const float* __restrict__ Wn1,
                                const float* __restrict__ Ws2, const float* __restrict__ Wn2,
                                __nv_bfloat16* __restrict__ hi, __nv_bfloat16* __restrict__ lo)
{
    int idx = blockIdx.x * 256 + threadIdx.x;   // layer*131072 + n*256 + k
    int layer = idx >> 17;
    int rem = idx & 131071;
    int n = rem >> 8, k = rem & 255;
    const float* W = layer ? (n < 256 ? Ws2 : Wn2) : (n < 256 ? Ws1 : Wn1);
    float v = W[k * 256 + (n & 255)];
    __nv_bfloat16 h = __float2bfloat16(v);
    hi[idx] = h;
    lo[idx] = __float2bfloat16(v - __bfloat162float(h));
}

// ---------------------------------------------------------------------------
// Tensor-core GEMM via mma.sync (bf16 3-product split, fp32 accum):
//   [outSelf | outSupp][M,256] = A[M,256] @ Bt^T   (Bt = [512][256], k-contig)
// Block tile 128x128, 8 warps (2 m x 4 n), warp tile 64x32, K chunk 32.
// SMEM rows padded to 80 B -> conflict-free ldmatrix.
// ---------------------------------------------------------------------------
#define PITCH 80

__global__ void __launch_bounds__(256, 1)
gemm_mma_kernel(const __nv_bfloat16* __restrict__ Ahi, const __nv_bfloat16* __restrict__ Alo,
                const __nv_bfloat16* __restrict__ Bthi, const __nv_bfloat16* __restrict__ Btlo,
                float* __restrict__ outSelf, float* __restrict__ outSupp, int M)
{
    __shared__ __align__(16) unsigned char sA[2][128 * PITCH];   // [plane][row*PITCH + kbyte]
    __shared__ __align__(16) unsigned char sB[2][128 * PITCH];

    int tid = threadIdx.x, wid = tid >> 5, lane = tid & 31;
    int wm = wid >> 2, wn = wid & 3;
    int rowTile = blockIdx.x * 128;
    int nGlob = blockIdx.y * 128;
    float* out = (nGlob < 256) ? outSelf : outSupp;
    int colBase = nGlob & 255;

    float acc[4][4][4];
    #pragma unroll
    for (int mt = 0; mt < 4; mt++)
        #pragma unroll
        for (int nt = 0; nt < 4; nt++)
            #pragma unroll
            for (int q = 0; q < 4; q++) acc[mt][nt][q] = 0.f;

    // per-thread ldmatrix base addresses
    uint32_t aBase0 = (uint32_t)__cvta_generic_to_shared(&sA[0][0]);
    uint32_t aBase1 = (uint32_t)__cvta_generic_to_shared(&sA[1][0]);
    uint32_t bBase0 = (uint32_t)__cvta_generic_to_shared(&sB[0][0]);
    uint32_t bBase1 = (uint32_t)__cvta_generic_to_shared(&sB[1][0]);
    uint32_t aOff = (uint32_t)((wm * 64 + (lane & 15)) * PITCH + (lane >> 4) * 16);
    uint32_t bOff = (uint32_t)((wn * 32 + ((lane >> 4) & 1) * 8 + (lane & 7)) * PITCH
                               + ((lane >> 3) & 1) * 16);

    for (int chunk = 0; chunk < 8; chunk++) {
        int kbase = chunk * 32;
        // fill SMEM: A and B, 2 planes each, 128 rows x 32 k (64 B = 4 uint4/row)
        #pragma unroll
        for (int rep = 0; rep < 4; rep++) {
            int i = tid + rep * 256;                 // 0..1023
            int plane = i >> 9;
            int rem = i & 511;
            int row = rem >> 2;
            int q = rem & 3;
            const __nv_bfloat16* sp = plane ? Alo : Ahi;
            uint4 v = *(const uint4*)(sp + (size_t)(rowTile + row) * 256 + kbase + q * 8);
            *(uint4*)&sA[plane][row * PITCH + q * 16] = v;
        }
        #pragma unroll
        for (int rep = 0; rep < 4; rep++) {
            int i = tid + rep * 256;
            int plane = i >> 9;
            int rem = i & 511;
            int row = rem >> 2;
            int q = rem & 3;
            const __nv_bfloat16* sp = plane ? Btlo : Bthi;
            uint4 v = *(const uint4*)(sp + (size_t)(nGlob + row) * 256 + kbase + q * 8);
            *(uint4*)&sB[plane][row * PITCH + q * 16] = v;
        }
        __syncthreads();

        #pragma unroll
        for (int kstep = 0; kstep < 2; kstep++) {
            uint32_t kb = kstep * 32;                 // 16 bf16 = 32 bytes
            uint32_t Af[4][4], Bh[2][4], Bl[2][4];
            // A hi fragments (4 m16 tiles)
            #pragma unroll
            for (int mt = 0; mt < 4; mt++)
                ldsm4(Af[mt], aBase0 + aOff + mt * (16 * PITCH) + kb);
            // B hi fragments (2 n16 tiles = 4 n8 tiles)
            #pragma unroll
            for (int bt = 0; bt < 2; bt++)
                ldsm4(Bh[bt], bBase0 + bOff + bt * (16 * PITCH) + kb);
            // Ah * Bh
            #pragma unroll
            for (int mt = 0; mt < 4; mt++)
                #pragma unroll
                for (int bt = 0; bt < 2; bt++) {
                    mma16816(acc[mt][bt * 2 + 0], Af[mt], &Bh[bt][0]);
                    mma16816(acc[mt][bt * 2 + 1], Af[mt], &Bh[bt][2]);
                }
            // B lo
            #pragma unroll
            for (int bt = 0; bt < 2; bt++)
                ldsm4(Bl[bt], bBase1 + bOff + bt * (16 * PITCH) + kb);
            // Ah * Bl
            #pragma unroll
            for (int mt = 0; mt < 4; mt++)
                #pragma unroll
                for (int bt = 0; bt < 2; bt++) {
                    mma16816(acc[mt][bt * 2 + 0], Af[mt], &Bl[bt][0]);
                    mma16816(acc[mt][bt * 2 + 1], Af[mt], &Bl[bt][2]);
                }
            // A lo (overwrite Af)
            #pragma unroll
            for (int mt = 0; mt < 4; mt++)
                ldsm4(Af[mt], aBase1 + aOff + mt * (16 * PITCH) + kb);
            // Al * Bh
            #pragma unroll
            for (int mt = 0; mt < 4; mt++)
                #pragma unroll
                for (int bt = 0; bt < 2; bt++) {
                    mma16816(acc[mt][bt * 2 + 0], Af[mt], &Bh[bt][0]);
                    mma16816(acc[mt][bt * 2 + 1], Af[mt], &Bh[bt][2]);
                }
        }
        __syncthreads();
    }

    // Epilogue: c0,c1 -> (row, col..col+1); c2,c3 -> (row+8, col..col+1)
    int rBase = rowTile + wm * 64 + (lane >> 2);
    int cBase = colBase + wn * 32 + (lane & 3) * 2;
    #pragma unroll
    for (int mt = 0; mt < 4; mt++) {
        int r0 = rBase + mt * 16;
        #pragma unroll
        for (int nt = 0; nt < 4; nt++) {
            int c = cBase + nt * 8;
            if (r0 < M)
                *(float2*)(out + (size_t)r0 * 256 + c) = make_float2(acc[mt][nt][0], acc[mt][nt][1]);
            if (r0 + 8 < M)
                *(float2*)(out + (size_t)(r0 + 8) * 256 + c) = make_float2(acc[mt][nt][2], acc[mt][nt][3]);
        }
    }
}

// ---------------------------------------------------------------------------
// Aggregation: out[i] = relu(self[i] + sum_{edges of i} val * support[col] + b)
// ---------------------------------------------------------------------------
__global__ void __launch_bounds__(256)
agg1_kernel(const float* __restrict__ selfbuf, const float* __restrict__ support,
            const int* __restrict__ rowptr, const int* __restrict__ cols,
            const float* __restrict__ vals, const float* __restrict__ bias,
            float* __restrict__ out)
{
    int i = blockIdx.x;
    int j = threadIdx.x;
    __shared__ int   sc[128];
    __shared__ float sv[128];
    int s = rowptr[i], e = rowptr[i + 1];
    float acc = selfbuf[(size_t)i * FF + j];
    for (int b0 = s; b0 < e; b0 += 128) {
        int n = min(128, e - b0);
        __syncthreads();
        if (j < n) { sc[j] = cols[b0 + j]; sv[j] = vals[b0 + j]; }
        __syncthreads();
        #pragma unroll 4
        for (int t = 0; t < n; t++)
            acc = fmaf(sv[t], support[(size_t)sc[t] * FF + j], acc);
    }
    out[(size_t)i * FF + j] = fmaxf(acc + bias[j], 0.f);
}

__global__ void __launch_bounds__(256)
agg2_kernel(const float* __restrict__ selfbuf, const float* __restrict__ support,
            const int* __restrict__ rowptr, const int* __restrict__ cols,
            const float* __restrict__ vals, const float* __restrict__ bias,
            const float* __restrict__ x, const float* __restrict__ z,
            float* __restrict__ xenc)
{
    int i = blockIdx.x;
    int j = threadIdx.x;
    __shared__ int   sc[128];
    __shared__ float sv[128];
    int s = rowptr[i], e = rowptr[i + 1];
    float acc = selfbuf[(size_t)i * FF + j];
    for (int b0 = s; b0 < e; b0 += 128) {
        int n = min(128, e - b0);
        __syncthreads();
        if (j < n) { sc[j] = cols[b0 + j]; sv[j] = vals[b0 + j]; }
        __syncthreads();
        #pragma unroll 4
        for (int t = 0; t < n; t++)
            acc = fmaf(sv[t], support[(size_t)sc[t] * FF + j], acc);
    }
    float x2 = fmaxf(acc + bias[j], 0.f);
    float zi = z[i];
    xenc[(size_t)i * FF + j] = (1.f - zi) * x[(size_t)i * FF + j] + zi * x2;
}

// ---------------------------------------------------------------------------
// Gates
// ---------------------------------------------------------------------------
__global__ void gate_logits_kernel(const float* __restrict__ x,
                                   const float* __restrict__ w1, const float* __restrict__ b1,
                                   const float* __restrict__ w2, const float* __restrict__ b2,
                                   float* __restrict__ l1, float* __restrict__ l2, int n)
{
    int warp = (blockIdx.x * blockDim.x + threadIdx.x) >> 5;
    int lane = threadIdx.x & 31;
    if (warp >= n) return;
    const float* xr = x + (size_t)warp * FF;
    float s1 = 0.f, s2 = 0.f;
    #pragma unroll
    for (int q = 0; q < 8; q++) {
        int k = lane + q * 32;
        float xv = xr[k];
        s1 = fmaf(xv, w1[k], s1);
        s2 = fmaf(xv, w2[k], s2);
    }
    #pragma unroll
    for (int o = 16; o > 0; o >>= 1) {
        s1 += __shfl_down_sync(0xFFFFFFFFu, s1, o);
        s2 += __shfl_down_sync(0xFFFFFFFFu, s2, o);
    }
    if (lane == 0) { l1[warp] = s1 + b1[0]; l2[warp] = s2 + b2[0]; }
}

__global__ void reduce_max_kernel(const float* __restrict__ l1, const float* __restrict__ l2,
                                  float* __restrict__ red, int n)
{
    float m1 = -3.4e38f, m2 = -3.4e38f;
    for (int i = threadIdx.x; i < n; i += blockDim.x) {
        m1 = fmaxf(m1, l1[i]); m2 = fmaxf(m2, l2[i]);
    }
    __shared__ float sh1[32], sh2[32];
    int lane = threadIdx.x & 31, w = threadIdx.x >> 5;
    #pragma unroll
    for (int o = 16; o > 0; o >>= 1) {
        m1 = fmaxf(m1, __shfl_xor_sync(0xFFFFFFFFu, m1, o));
        m2 = fmaxf(m2, __shfl_xor_sync(0xFFFFFFFFu, m2, o));
    }
    if (lane == 0) { sh1[w] = m1; sh2[w] = m2; }
    __syncthreads();
    if (w == 0) {
        m1 = (lane < (int)(blockDim.x >> 5)) ? sh1[lane] : -3.4e38f;
        m2 = (lane < (int)(blockDim.x >> 5)) ? sh2[lane] : -3.4e38f;
        #pragma unroll
        for (int o = 16; o > 0; o >>= 1) {
            m1 = fmaxf(m1, __shfl_xor_sync(0xFFFFFFFFu, m1, o));
            m2 = fmaxf(m2, __shfl_xor_sync(0xFFFFFFFFu, m2, o));
        }
        if (lane == 0) { red[0] = m1; red[1] = m2; }
    }
}

__global__ void reduce_sumexp_kernel(const float* __restrict__ l1, const float* __restrict__ l2,
                                     float* __restrict__ red, int n)
{
    float m1 = red[0], m2 = red[1];
    float s1 = 0.f, s2 = 0.f;
    for (int i = threadIdx.x; i < n; i += blockDim.x) {
        s1 += expf(l1[i] - m1);
        s2 += expf(l2[i] - m2);
    }
    __shared__ float sh1[32], sh2[32];
    int lane = threadIdx.x & 31, w = threadIdx.x >> 5;
    #pragma unroll
    for (int o = 16; o > 0; o >>= 1) {
        s1 += __shfl_xor_sync(0xFFFFFFFFu, s1, o);
        s2 += __shfl_xor_sync(0xFFFFFFFFu, s2, o);
    }
    if (lane == 0) { sh1[w] = s1; sh2[w] = s2; }
    __syncthreads();
    if (w == 0) {
        s1 = (lane < (int)(blockDim.x >> 5)) ? sh1[lane] : 0.f;
        s2 = (lane < (int)(blockDim.x >> 5)) ? sh2[lane] : 0.f;
        #pragma unroll
        for (int o = 16; o > 0; o >>= 1) {
            s1 += __shfl_xor_sync(0xFFFFFFFFu, s1, o);
            s2 += __shfl_xor_sync(0xFFFFFFFFu, s2, o);
        }
        if (lane == 0) { red[2] = s1; red[3] = s2; }
    }
}

__global__ void rz_kernel(const float* __restrict__ l1, const float* __restrict__ l2,
                          const float* __restrict__ red,
                          float* __restrict__ r, float* __restrict__ z, int n)
{
    int i = blockIdx.x * blockDim.x + threadIdx.x;
    if (i < n) {
        r[i] = expf(l1[i] - red[0]) / red[2];
        z[i] = expf(l2[i] - red[1]) / red[3];
    }
}

// ---------------------------------------------------------------------------
// Mean over nodes + final projection
// ---------------------------------------------------------------------------
__global__ void colsum_kernel(const float* __restrict__ xenc, float* __restrict__ colacc, int n)
{
    int j = threadIdx.x;
    int r0 = blockIdx.x * 64;
    int r1 = min(r0 + 64, n);
    float s = 0.f;
    for (int r = r0; r < r1; r++) s += xenc[(size_t)r * FF + j];
    atomicAdd(&colacc[j], s);
}

__global__ void final_kernel(const float* __restrict__ colacc,
                             const float* __restrict__ e2p_w, const float* __restrict__ e2p_b,
                             float* __restrict__ out)
{
    int o = threadIdx.x;
    float s = 0.f;
    #pragma unroll 8
    for (int k = 0; k < FF; k++)
        s = fmaf(colacc[k] * (1.0f / (float)NN), e2p_w[(size_t)k * NOUT + o], s);
    out[o] = s + e2p_b[o];
}

// ---------------------------------------------------------------------------
// Launch
// ---------------------------------------------------------------------------
extern "C" void kernel_launch(void* const* d_in, const int* in_sizes, int n_in,
                              void* d_out, int out_size)
{
    const float* inputs   = (const float*)d_in[0];
    const int*   edge_row = (const int*)  d_in[1];
    const int*   edge_col = (const int*)  d_in[2];
    const float* edge_val = (const float*)d_in[3];
    const float* W_self1  = (const float*)d_in[4];
    const float* W_nb1    = (const float*)d_in[5];
    const float* b1       = (const float*)d_in[6];
    const float* W_self2  = (const float*)d_in[7];
    const float* W_nb2    = (const float*)d_in[8];
    const float* b2       = (const float*)d_in[9];
    const float* gate1_w  = (const float*)d_in[10];
    const float* gate1_b  = (const float*)d_in[11];
    const float* gate2_w  = (const float*)d_in[12];
    const float* gate2_b  = (const float*)d_in[13];
    const float* e2p_w    = (const float*)d_in[14];
    const float* e2p_b    = (const float*)d_in[15];

    float* xenc = (float*)d_out;
    float* out  = (float*)d_out + (size_t)NN * FF;

    int*   p_cursor;  cudaGetSymbolAddress((void**)&p_cursor,  g_cursor);
    int*   p_rowptr;  cudaGetSymbolAddress((void**)&p_rowptr,  g_rowptr);
    int*   p_cols;    cudaGetSymbolAddress((void**)&p_cols,    g_cols);
    float* p_vals;    cudaGetSymbolAddress((void**)&p_vals,    g_vals);
    float* p_self;    cudaGetSymbolAddress((void**)&p_self,    g_self);
    float* p_support; cudaGetSymbolAddress((void**)&p_support, g_support);
    float* p_x;       cudaGetSymbolAddress((void**)&p_x,       g_x);
    float* p_l1;      cudaGetSymbolAddress((void**)&p_l1,      g_l1);
    float* p_l2;      cudaGetSymbolAddress((void**)&p_l2,      g_l2);
    float* p_r;       cudaGetSymbolAddress((void**)&p_r,       g_r);
    float* p_z;       cudaGetSymbolAddress((void**)&p_z,       g_z);
    float* p_red;     cudaGetSymbolAddress((void**)&p_red,     g_red);
    float* p_colsum;  cudaGetSymbolAddress((void**)&p_colsum,  g_colsum);
    __nv_bfloat16* p_Ahi;  cudaGetSymbolAddress((void**)&p_Ahi,  g_Ahi);
    __nv_bfloat16* p_Alo;  cudaGetSymbolAddress((void**)&p_Alo,  g_Alo);
    __nv_bfloat16* p_Bthi; cudaGetSymbolAddress((void**)&p_Bthi, g_Bthi);
    __nv_bfloat16* p_Btlo; cudaGetSymbolAddress((void**)&p_Btlo, g_Btlo);

    const int TB = 256;
    dim3 gemmGrid(MPAD / 128, 4);           // y covers N=512 (self 0-255 | supp 256-511)
    int convAblocks = (MPAD * 64) / 256;

    // CSR build
    zero_kernel<<<(NN + TB - 1) / TB, TB>>>(p_cursor, p_colsum, p_red, NN);
    hist_kernel<<<(EE + TB - 1) / TB, TB>>>(edge_row, p_cursor, EE);
    scan_kernel<<<1, 1024>>>(p_cursor, p_rowptr, NN);
    copy_cursor_kernel<<<(NN + TB - 1) / TB, TB>>>(p_rowptr, p_cursor, NN);
    scatter_kernel<<<(EE + TB - 1) / TB, TB>>>(edge_row, edge_col, edge_val,
                                               p_cursor, p_cols, p_vals, EE);

    // Weight transpose + bf16 split (both layers)
    convertB_kernel<<<1024, TB>>>(W_self1, W_nb1, W_self2, W_nb2, p_Bthi, p_Btlo);

    // Layer 1: fused self+nb GEMM on tensor cores (mma.sync)
    convertA_kernel<<<convAblocks, TB>>>(inputs, nullptr, p_Ahi, p_Alo, NN);
    gemm_mma_kernel<<<gemmGrid, TB>>>(p_Ahi, p_Alo, p_Bthi, p_Btlo,
                                      p_self, p_support, NN);
    agg1_kernel<<<NN, TB>>>(p_self, p_support, p_rowptr, p_cols, p_vals, b1, p_x);

    // Gates
    gate_logits_kernel<<<(NN * 32 + TB - 1) / TB, TB>>>(p_x, gate1_w, gate1_b,
                                                        gate2_w, gate2_b, p_l1, p_l2, NN);
    reduce_max_kernel<<<1, 1024>>>(p_l1, p_l2, p_red, NN);
    reduce_sumexp_kernel<<<1, 1024>>>(p_l1, p_l2, p_red, NN);
    rz_kernel<<<(NN + TB - 1) / TB, TB>>>(p_l1, p_l2, p_red, p_r, p_z, NN);

    // Layer 2 (row-scale r fused into A conversion)
    convertA_kernel<<<convAblocks, TB>>>(p_x, p_r, p_Ahi, p_Alo, NN);
    gemm_mma_kernel<<<gemmGrid, TB>>>(p_Ahi, p_Alo,
                                      p_Bthi + 512 * 256, p_Btlo + 512 * 256,
                                      p_self, p_support, NN);
    agg2_kernel<<<NN, TB>>>(p_self, p_support, p_rowptr, p_cols, p_vals, b2,
                            p_x, p_z, xenc);

    // mean over nodes -> e2p
    colsum_kernel<<<(NN + 63) / 64, TB>>>(xenc, p_colsum, NN);
    final_kernel<<<1, NOUT>>>(p_colsum, e2p_w, e2p_b, out);
}

// round 10
// speedup vs baseline: 2.7051x; 1.4203x over previous
#include <cuda_runtime.h>
#include <cuda_bf16.h>
#include <cstdint>
#include <cstddef>

// Problem constants
#define NN   100000
#define EE   3200000
#define FF   256        // NFEAT == NHID
#define NOUT 128
#define MPAD 100096     // 782 * 128

// ---------------------------------------------------------------------------
// Scratch (static __device__ globals; no allocation anywhere)
// ---------------------------------------------------------------------------
__device__ int   g_cursor[NN];
__device__ int   g_rowptr[NN + 1];
__device__ int   g_cols[EE];
__device__ float g_vals[EE];
__device__ float g_self[(size_t)NN * FF];      // x @ W_self
__device__ float g_support[(size_t)NN * FF];   // x @ W_nb
__device__ float g_x[(size_t)NN * FF];         // layer-1 output
__device__ float g_l1[NN], g_l2[NN];
__device__ float g_r[NN], g_z[NN];
__device__ float g_red[4];
__device__ float g_colsum[FF];
// bf16-split operands
__device__ __nv_bfloat16 g_Ahi[(size_t)MPAD * FF];
__device__ __nv_bfloat16 g_Alo[(size_t)MPAD * FF];
__device__ __nv_bfloat16 g_Bthi[2 * 512 * 256];   // [layer][n][k], n = [self | nb]
__device__ __nv_bfloat16 g_Btlo[2 * 512 * 256];

// ---------------------------------------------------------------------------
// mma.sync / ldmatrix / cp.async helpers (baseline PTX, no 'a'-suffix features)
// ---------------------------------------------------------------------------
__device__ __forceinline__ void ldsm4(uint32_t* r, uint32_t addr) {
    asm volatile("ldmatrix.sync.aligned.m8n8.x4.shared.b16 {%0,%1,%2,%3}, [%4];"
        : "=r"(r[0]), "=r"(r[1]), "=r"(r[2]), "=r"(r[3]) : "r"(addr));
}

__device__ __forceinline__ void mma16816(float* c, const uint32_t* a, const uint32_t* b) {
    asm volatile("mma.sync.aligned.m16n8k16.row.col.f32.bf16.bf16.f32 "
        "{%0,%1,%2,%3}, {%4,%5,%6,%7}, {%8,%9}, {%0,%1,%2,%3};"
        : "+f"(c[0]), "+f"(c[1]), "+f"(c[2]), "+f"(c[3])
        : "r"(a[0]), "r"(a[1]), "r"(a[2]), "r"(a[3]), "r"(b[0]), "r"(b[1]));
}

__device__ __forceinline__ void cpasync16(uint32_t saddr, const void* gaddr) {
    asm volatile("cp.async.cg.shared.global [%0], [%1], 16;"
        :: "r"(saddr), "l"(gaddr) : "memory");
}
#define CP_COMMIT() asm volatile("cp.async.commit_group;" ::: "memory")
#define CP_WAIT(n)  asm volatile("cp.async.wait_group %0;" :: "n"(n) : "memory")

// ---------------------------------------------------------------------------
// CSR construction
// ---------------------------------------------------------------------------
__global__ void zero_kernel(int* cursor, float* colsum, float* red, int n)
{
    int i = blockIdx.x * blockDim.x + threadIdx.x;
    if (i < n)   cursor[i] = 0;
    if (i < FF)  colsum[i] = 0.f;
    if (i < 4)   red[i] = 0.f;
}

__global__ void hist_kernel(const int* __restrict__ edge_row, int* __restrict__ cnt, int e)
{
    int i = blockIdx.x * blockDim.x + threadIdx.x;
    if (i < e) atomicAdd(&cnt[edge_row[i]], 1);
}

__global__ void scan_kernel(const int* __restrict__ cnt, int* __restrict__ rowptr, int n)
{
    __shared__ int warpsums[32];
    __shared__ int carry_s;
    int tid = threadIdx.x;
    int lane = tid & 31, w = tid >> 5;
    if (tid == 0) carry_s = 0;
    __syncthreads();
    for (int base = 0; base < n; base += 1024) {
        int i = base + tid;
        int v = (i < n) ? cnt[i] : 0;
        int incl = v;
        #pragma unroll
        for (int o = 1; o < 32; o <<= 1) {
            int t = __shfl_up_sync(0xFFFFFFFFu, incl, o);
            if (lane >= o) incl += t;
        }
        if (lane == 31) warpsums[w] = incl;
        __syncthreads();
        if (w == 0) {
            int s = warpsums[lane];
            #pragma unroll
            for (int o = 1; o < 32; o <<= 1) {
                int t = __shfl_up_sync(0xFFFFFFFFu, s, o);
                if (lane >= o) s += t;
            }
            warpsums[lane] = s;
        }
        __syncthreads();
        int blockIncl = incl + (w > 0 ? warpsums[w - 1] : 0);
        int carry = carry_s;
        if (i < n) rowptr[i] = carry + blockIncl - v;
        __syncthreads();
        if (tid == 1023) carry_s = carry + blockIncl;
        __syncthreads();
    }
    if (tid == 0) rowptr[n] = carry_s;
}

__global__ void copy_cursor_kernel(const int* __restrict__ rowptr, int* __restrict__ cursor, int n)
{
    int i = blockIdx.x * blockDim.x + threadIdx.x;
    if (i < n) cursor[i] = rowptr[i];
}

__global__ void scatter_kernel(const int* __restrict__ edge_row,
                               const int* __restrict__ edge_col,
                               const float* __restrict__ edge_val,
                               int* __restrict__ cursor,
                               int* __restrict__ cols, float* __restrict__ vals, int e)
{
    int i = blockIdx.x * blockDim.x + threadIdx.x;
    if (i < e) {
        int r = edge_row[i];
        int p = atomicAdd(&cursor[r], 1);
        cols[p] = edge_col[i];
        vals[p] = edge_val[i];
    }
}

// ---------------------------------------------------------------------------
// bf16-split conversions
// ---------------------------------------------------------------------------
__global__ void convertA_kernel(const float* __restrict__ src, const float* __restrict__ rowScale,
                                __nv_bfloat16* __restrict__ hi, __nv_bfloat16* __restrict__ lo, int M)
{
    size_t idx = (size_t)blockIdx.x * 256 + threadIdx.x;   // one float4 group (4 elems)
    int row = (int)(idx >> 6);                             // 64 groups per 256-wide row
    if (row >= MPAD) return;
    float4 v = make_float4(0.f, 0.f, 0.f, 0.f);
    if (row < M) {
        v = *(const float4*)(src + idx * 4);
        if (rowScale) { float s = rowScale[row]; v.x *= s; v.y *= s; v.z *= s; v.w *= s; }
    }
    __nv_bfloat16 h0 = __float2bfloat16(v.x), h1 = __float2bfloat16(v.y);
    __nv_bfloat16 h2 = __float2bfloat16(v.z), h3 = __float2bfloat16(v.w);
    __nv_bfloat16 l0 = __float2bfloat16(v.x - __bfloat162float(h0));
    __nv_bfloat16 l1 = __float2bfloat16(v.y - __bfloat162float(h1));
    __nv_bfloat16 l2 = __float2bfloat16(v.z - __bfloat162float(h2));
    __nv_bfloat16 l3 = __float2bfloat16(v.w - __bfloat162float(h3));
    __nv_bfloat162* hp = (__nv_bfloat162*)(hi + idx * 4);
    __nv_bfloat162* lp = (__nv_bfloat162*)(lo + idx * 4);
    hp[0] = __halves2bfloat162(h0, h1); hp[1] = __halves2bfloat162(h2, h3);
    lp[0] = __halves2bfloat162(l0, l1); lp[1] = __halves2bfloat162(l2, l3);
}

// Transpose + split all 4 weight matrices into [layer][n 0..511][k] bf16 hi/lo
__global__ void convertB_kernel(const float* __restrict__ Ws1, const float* __restrict__ Wn1,
                                const float* __restrict__ Ws2, const float* __restrict__ Wn2,
                                __nv_bfloat16* __restrict__ hi, __nv_bfloat16* __restrict__ lo)
{
    int idx = blockIdx.x * 256 + threadIdx.x;   // layer*131072 + n*256 + k
    int layer = idx >> 17;
    int rem = idx & 131071;
    int n = rem >> 8, k = rem & 255;
    const float* W = layer ? (n < 256 ? Ws2 : Wn2) : (n < 256 ? Ws1 : Wn1);
    float v = W[k * 256 + (n & 255)];
    __nv_bfloat16 h = __float2bfloat16(v);
    hi[idx] = h;
    lo[idx] = __float2bfloat16(v - __bfloat162float(h));
}

// ---------------------------------------------------------------------------
// Tensor-core GEMM via mma.sync (bf16 3-product split, fp32 accum):
//   [outSelf | outSupp][M,256] = A[M,256] @ Bt^T   (Bt = [512][256], k-contig)
// Block tile 128x128, 8 warps (2 m x 4 n), warp tile 64x32, K chunk 32.
// 2-stage cp.async double buffer. SMEM rows 80 B pitch (conflict-free ldmatrix).
// Dynamic SMEM: 2 stages x (A 2 planes + B 2 planes) x 128 rows x 80 B = 81920 B.
// ---------------------------------------------------------------------------
#define PITCH 80
#define PLANE_BYTES (128 * PITCH)          // 10240
#define STAGE_BYTES (4 * PLANE_BYTES)      // 40960: Ahi, Alo, Bhi, Blo
#define GEMM_SMEM   (2 * STAGE_BYTES)      // 81920

__device__ __forceinline__ void gemm_load_chunk(
    const __nv_bfloat16* __restrict__ Ahi, const __nv_bfloat16* __restrict__ Alo,
    const __nv_bfloat16* __restrict__ Bthi, const __nv_bfloat16* __restrict__ Btlo,
    uint32_t stageAddr, int rowTile, int nGlob, int kbase, int tid)
{
    #pragma unroll
    for (int rep = 0; rep < 4; rep++) {
        int i = tid + rep * 256;               // 0..1023
        int plane = i >> 9;
        int rem = i & 511;
        int row = rem >> 2;
        int q = rem & 3;
        const __nv_bfloat16* sp = plane ? Alo : Ahi;
        cpasync16(stageAddr + plane * PLANE_BYTES + row * PITCH + q * 16,
                  sp + (size_t)(rowTile + row) * 256 + kbase + q * 8);
    }
    #pragma unroll
    for (int rep = 0; rep < 4; rep++) {
        int i = tid + rep * 256;
        int plane = i >> 9;
        int rem = i & 511;
        int row = rem >> 2;
        int q = rem & 3;
        const __nv_bfloat16* sp = plane ? Btlo : Bthi;
        cpasync16(stageAddr + (2 + plane) * PLANE_BYTES + row * PITCH + q * 16,
                  sp + (size_t)(nGlob + row) * 256 + kbase + q * 8);
    }
}

__global__ void __launch_bounds__(256)
gemm_mma_kernel(const __nv_bfloat16* __restrict__ Ahi, const __nv_bfloat16* __restrict__ Alo,
                const __nv_bfloat16* __restrict__ Bthi, const __nv_bfloat16* __restrict__ Btlo,
                float* __restrict__ outSelf, float* __restrict__ outSupp, int M)
{
    extern __shared__ __align__(16) unsigned char dsm[];
    uint32_t smemBase = (uint32_t)__cvta_generic_to_shared(dsm);

    int tid = threadIdx.x, wid = tid >> 5, lane = tid & 31;
    int wm = wid >> 2, wn = wid & 3;
    int rowTile = blockIdx.x * 128;
    int nGlob = blockIdx.y * 128;
    float* out = (nGlob < 256) ? outSelf : outSupp;
    int colBase = nGlob & 255;

    float acc[4][4][4];
    #pragma unroll
    for (int mt = 0; mt < 4; mt++)
        #pragma unroll
        for (int nt = 0; nt < 4; nt++)
            #pragma unroll
            for (int q = 0; q < 4; q++) acc[mt][nt][q] = 0.f;

    uint32_t aOff = (uint32_t)((wm * 64 + (lane & 15)) * PITCH + (lane >> 4) * 16);
    uint32_t bOff = (uint32_t)((wn * 32 + ((lane >> 4) & 1) * 8 + (lane & 7)) * PITCH
                               + ((lane >> 3) & 1) * 16);

    // prologue: stage 0 <- chunk 0
    gemm_load_chunk(Ahi, Alo, Bthi, Btlo, smemBase, rowTile, nGlob, 0, tid);
    CP_COMMIT();

    for (int c = 0; c < 8; c++) {
        if (c < 7) {
            gemm_load_chunk(Ahi, Alo, Bthi, Btlo,
                            smemBase + ((c + 1) & 1) * STAGE_BYTES,
                            rowTile, nGlob, (c + 1) * 32, tid);
            CP_COMMIT();
            CP_WAIT(1);
        } else {
            CP_WAIT(0);
        }
        __syncthreads();

        uint32_t st = smemBase + (c & 1) * STAGE_BYTES;
        uint32_t aBase0 = st;
        uint32_t aBase1 = st + PLANE_BYTES;
        uint32_t bBase0 = st + 2 * PLANE_BYTES;
        uint32_t bBase1 = st + 3 * PLANE_BYTES;

        #pragma unroll
        for (int kstep = 0; kstep < 2; kstep++) {
            uint32_t kb = kstep * 32;                 // 16 bf16 = 32 bytes
            uint32_t Af[4][4], Bh[2][4], Bl[2][4];
            #pragma unroll
            for (int mt = 0; mt < 4; mt++)
                ldsm4(Af[mt], aBase0 + aOff + mt * (16 * PITCH) + kb);
            #pragma unroll
            for (int bt = 0; bt < 2; bt++)
                ldsm4(Bh[bt], bBase0 + bOff + bt * (16 * PITCH) + kb);
            // Ah * Bh
            #pragma unroll
            for (int mt = 0; mt < 4; mt++)
                #pragma unroll
                for (int bt = 0; bt < 2; bt++) {
                    mma16816(acc[mt][bt * 2 + 0], Af[mt], &Bh[bt][0]);
                    mma16816(acc[mt][bt * 2 + 1], Af[mt], &Bh[bt][2]);
                }
            #pragma unroll
            for (int bt = 0; bt < 2; bt++)
                ldsm4(Bl[bt], bBase1 + bOff + bt * (16 * PITCH) + kb);
            // Ah * Bl
            #pragma unroll
            for (int mt = 0; mt < 4; mt++)
                #pragma unroll
                for (int bt = 0; bt < 2; bt++) {
                    mma16816(acc[mt][bt * 2 + 0], Af[mt], &Bl[bt][0]);
                    mma16816(acc[mt][bt * 2 + 1], Af[mt], &Bl[bt][2]);
                }
            #pragma unroll
            for (int mt = 0; mt < 4; mt++)
                ldsm4(Af[mt], aBase1 + aOff + mt * (16 * PITCH) + kb);
            // Al * Bh
            #pragma unroll
            for (int mt = 0; mt < 4; mt++)
                #pragma unroll
                for (int bt = 0; bt < 2; bt++) {
                    mma16816(acc[mt][bt * 2 + 0], Af[mt], &Bh[bt][0]);
                    mma16816(acc[mt][bt * 2 + 1], Af[mt], &Bh[bt][2]);
                }
        }
        __syncthreads();
    }

    // Epilogue
    int rBase = rowTile + wm * 64 + (lane >> 2);
    int cBase = colBase + wn * 32 + (lane & 3) * 2;
    #pragma unroll
    for (int mt = 0; mt < 4; mt++) {
        int r0 = rBase + mt * 16;
        #pragma unroll
        for (int nt = 0; nt < 4; nt++) {
            int c = cBase + nt * 8;
            if (r0 < M)
                *(float2*)(out + (size_t)r0 * 256 + c) = make_float2(acc[mt][nt][0], acc[mt][nt][1]);
            if (r0 + 8 < M)
                *(float2*)(out + (size_t)(r0 + 8) * 256 + c) = make_float2(acc[mt][nt][2], acc[mt][nt][3]);
        }
    }
}

// ---------------------------------------------------------------------------
// Aggregation (128 threads, float2 per thread):
//   out[i] = relu(self[i] + sum_{edges of i} val * support[col] + b)
// agg1 additionally computes the two gate logits for row i (fused block reduce).
// ---------------------------------------------------------------------------
__global__ void __launch_bounds__(128)
agg1_kernel(const float* __restrict__ selfbuf, const float* __restrict__ support,
            const int* __restrict__ rowptr, const int* __restrict__ cols,
            const float* __restrict__ vals, const float* __restrict__ bias,
            const float* __restrict__ w1, const float* __restrict__ b1,
            const float* __restrict__ w2, const float* __restrict__ b2,
            float* __restrict__ out, float* __restrict__ l1, float* __restrict__ l2)
{
    int i = blockIdx.x;
    int j = threadIdx.x;               // column pair (2j, 2j+1)
    __shared__ int   sc[128];
    __shared__ float sv[128];
    __shared__ float red1[4], red2[4];
    int s = rowptr[i], e = rowptr[i + 1];
    float2 acc = *(const float2*)(selfbuf + (size_t)i * FF + j * 2);
    const float* supJ = support + j * 2;
    for (int b0 = s; b0 < e; b0 += 128) {
        int n = min(128, e - b0);
        __syncthreads();
        if (j < n) { sc[j] = cols[b0 + j]; sv[j] = vals[b0 + j]; }
        __syncthreads();
        #pragma unroll 8
        for (int t = 0; t < n; t++) {
            float2 p = *(const float2*)(supJ + (size_t)sc[t] * FF);
            acc.x = fmaf(sv[t], p.x, acc.x);
            acc.y = fmaf(sv[t], p.y, acc.y);
        }
    }
    acc.x = fmaxf(acc.x + bias[j * 2], 0.f);
    acc.y = fmaxf(acc.y + bias[j * 2 + 1], 0.f);
    *(float2*)(out + (size_t)i * FF + j * 2) = acc;

    // fused gate logits: dot(x_row, w1/w2) via block reduce
    float g1 = acc.x * w1[j * 2] + acc.y * w1[j * 2 + 1];
    float g2 = acc.x * w2[j * 2] + acc.y * w2[j * 2 + 1];
    #pragma unroll
    for (int o = 16; o > 0; o >>= 1) {
        g1 += __shfl_xor_sync(0xFFFFFFFFu, g1, o);
        g2 += __shfl_xor_sync(0xFFFFFFFFu, g2, o);
    }
    int lane = j & 31, w = j >> 5;
    if (lane == 0) { red1[w] = g1; red2[w] = g2; }
    __syncthreads();
    if (j == 0) {
        l1[i] = red1[0] + red1[1] + red1[2] + red1[3] + b1[0];
        l2[i] = red2[0] + red2[1] + red2[2] + red2[3] + b2[0];
    }
}

__global__ void __launch_bounds__(128)
agg2_kernel(const float* __restrict__ selfbuf, const float* __restrict__ support,
            const int* __restrict__ rowptr, const int* __restrict__ cols,
            const float* __restrict__ vals, const float* __restrict__ bias,
            const float* __restrict__ x, const float* __restrict__ z,
            float* __restrict__ xenc)
{
    int i = blockIdx.x;
    int j = threadIdx.x;
    __shared__ int   sc[128];
    __shared__ float sv[128];
    int s = rowptr[i], e = rowptr[i + 1];
    float2 acc = *(const float2*)(selfbuf + (size_t)i * FF + j * 2);
    const float* supJ = support + j * 2;
    for (int b0 = s; b0 < e; b0 += 128) {
        int n = min(128, e - b0);
        __syncthreads();
        if (j < n) { sc[j] = cols[b0 + j]; sv[j] = vals[b0 + j]; }
        __syncthreads();
        #pragma unroll 8
        for (int t = 0; t < n; t++) {
            float2 p = *(const float2*)(supJ + (size_t)sc[t] * FF);
            acc.x = fmaf(sv[t], p.x, acc.x);
            acc.y = fmaf(sv[t], p.y, acc.y);
        }
    }
    float x2a = fmaxf(acc.x + bias[j * 2], 0.f);
    float x2b = fmaxf(acc.y + bias[j * 2 + 1], 0.f);
    float zi = z[i];
    float2 xv = *(const float2*)(x + (size_t)i * FF + j * 2);
    float2 r;
    r.x = (1.f - zi) * xv.x + zi * x2a;
    r.y = (1.f - zi) * xv.y + zi * x2b;
    *(float2*)(xenc + (size_t)i * FF + j * 2) = r;
}

// ---------------------------------------------------------------------------
// Softmax reductions over node logits
// ---------------------------------------------------------------------------
__global__ void reduce_max_kernel(const float* __restrict__ l1, const float* __restrict__ l2,
                                  float* __restrict__ red, int n)
{
    float m1 = -3.4e38f, m2 = -3.4e38f;
    for (int i = threadIdx.x; i < n; i += blockDim.x) {
        m1 = fmaxf(m1, l1[i]); m2 = fmaxf(m2, l2[i]);
    }
    __shared__ float sh1[32], sh2[32];
    int lane = threadIdx.x & 31, w = threadIdx.x >> 5;
    #pragma unroll
    for (int o = 16; o > 0; o >>= 1) {
        m1 = fmaxf(m1, __shfl_xor_sync(0xFFFFFFFFu, m1, o));
        m2 = fmaxf(m2, __shfl_xor_sync(0xFFFFFFFFu, m2, o));
    }
    if (lane == 0) { sh1[w] = m1; sh2[w] = m2; }
    __syncthreads();
    if (w == 0) {
        m1 = (lane < (int)(blockDim.x >> 5)) ? sh1[lane] : -3.4e38f;
        m2 = (lane < (int)(blockDim.x >> 5)) ? sh2[lane] : -3.4e38f;
        #pragma unroll
        for (int o = 16; o > 0; o >>= 1) {
            m1 = fmaxf(m1, __shfl_xor_sync(0xFFFFFFFFu, m1, o));
            m2 = fmaxf(m2, __shfl_xor_sync(0xFFFFFFFFu, m2, o));
        }
        if (lane == 0) { red[0] = m1; red[1] = m2; }
    }
}

__global__ void reduce_sumexp_kernel(const float* __restrict__ l1, const float* __restrict__ l2,
                                     float* __restrict__ red, int n)
{
    float m1 = red[0], m2 = red[1];
    float s1 = 0.f, s2 = 0.f;
    for (int i = threadIdx.x; i < n; i += blockDim.x) {
        s1 += expf(l1[i] - m1);
        s2 += expf(l2[i] - m2);
    }
    __shared__ float sh1[32], sh2[32];
    int lane = threadIdx.x & 31, w = threadIdx.x >> 5;
    #pragma unroll
    for (int o = 16; o > 0; o >>= 1) {
        s1 += __shfl_xor_sync(0xFFFFFFFFu, s1, o);
        s2 += __shfl_xor_sync(0xFFFFFFFFu, s2, o);
    }
    if (lane == 0) { sh1[w] = s1; sh2[w] = s2; }
    __syncthreads();
    if (w == 0) {
        s1 = (lane < (int)(blockDim.x >> 5)) ? sh1[lane] : 0.f;
        s2 = (lane < (int)(blockDim.x >> 5)) ? sh2[lane] : 0.f;
        #pragma unroll
        for (int o = 16; o > 0; o >>= 1) {
            s1 += __shfl_xor_sync(0xFFFFFFFFu, s1, o);
            s2 += __shfl_xor_sync(0xFFFFFFFFu, s2, o);
        }
        if (lane == 0) { red[2] = s1; red[3] = s2; }
    }
}

__global__ void rz_kernel(const float* __restrict__ l1, const float* __restrict__ l2,
                          const float* __restrict__ red,
                          float* __restrict__ r, float* __restrict__ z, int n)
{
    int i = blockIdx.x * blockDim.x + threadIdx.x;
    if (i < n) {
        r[i] = expf(l1[i] - red[0]) / red[2];
        z[i] = expf(l2[i] - red[1]) / red[3];
    }
}

// ---------------------------------------------------------------------------
// Mean over nodes + final projection
// ---------------------------------------------------------------------------
__global__ void colsum_kernel(const float* __restrict__ xenc, float* __restrict__ colacc, int n)
{
    int j = threadIdx.x;
    int r0 = blockIdx.x * 64;
    int r1 = min(r0 + 64, n);
    float s = 0.f;
    for (int r = r0; r < r1; r++) s += xenc[(size_t)r * FF + j];
    atomicAdd(&colacc[j], s);
}

__global__ void final_kernel(const float* __restrict__ colacc,
                             const float* __restrict__ e2p_w, const float* __restrict__ e2p_b,
                             float* __restrict__ out)
{
    int o = threadIdx.x;
    float s = 0.f;
    #pragma unroll 8
    for (int k = 0; k < FF; k++)
        s = fmaf(colacc[k] * (1.0f / (float)NN), e2p_w[(size_t)k * NOUT + o], s);
    out[o] = s + e2p_b[o];
}

// ---------------------------------------------------------------------------
// Launch
// ---------------------------------------------------------------------------
extern "C" void kernel_launch(void* const* d_in, const int* in_sizes, int n_in,
                              void* d_out, int out_size)
{
    const float* inputs   = (const float*)d_in[0];
    const int*   edge_row = (const int*)  d_in[1];
    const int*   edge_col = (const int*)  d_in[2];
    const float* edge_val = (const float*)d_in[3];
    const float* W_self1  = (const float*)d_in[4];
    const float* W_nb1    = (const float*)d_in[5];
    const float* b1       = (const float*)d_in[6];
    const float* W_self2  = (const float*)d_in[7];
    const float* W_nb2    = (const float*)d_in[8];
    const float* b2       = (const float*)d_in[9];
    const float* gate1_w  = (const float*)d_in[10];
    const float* gate1_b  = (const float*)d_in[11];
    const float* gate2_w  = (const float*)d_in[12];
    const float* gate2_b  = (const float*)d_in[13];
    const float* e2p_w    = (const float*)d_in[14];
    const float* e2p_b    = (const float*)d_in[15];

    float* xenc = (float*)d_out;
    float* out  = (float*)d_out + (size_t)NN * FF;

    int*   p_cursor;  cudaGetSymbolAddress((void**)&p_cursor,  g_cursor);
    int*   p_rowptr;  cudaGetSymbolAddress((void**)&p_rowptr,  g_rowptr);
    int*   p_cols;    cudaGetSymbolAddress((void**)&p_cols,    g_cols);
    float* p_vals;    cudaGetSymbolAddress((void**)&p_vals,    g_vals);
    float* p_self;    cudaGetSymbolAddress((void**)&p_self,    g_self);
    float* p_support; cudaGetSymbolAddress((void**)&p_support, g_support);
    float* p_x;       cudaGetSymbolAddress((void**)&p_x,       g_x);
    float* p_l1;      cudaGetSymbolAddress((void**)&p_l1,      g_l1);
    float* p_l2;      cudaGetSymbolAddress((void**)&p_l2,      g_l2);
    float* p_r;       cudaGetSymbolAddress((void**)&p_r,       g_r);
    float* p_z;       cudaGetSymbolAddress((void**)&p_z,       g_z);
    float* p_red;     cudaGetSymbolAddress((void**)&p_red,     g_red);
    float* p_colsum;  cudaGetSymbolAddress((void**)&p_colsum,  g_colsum);
    __nv_bfloat16* p_Ahi;  cudaGetSymbolAddress((void**)&p_Ahi,  g_Ahi);
    __nv_bfloat16* p_Alo;  cudaGetSymbolAddress((void**)&p_Alo,  g_Alo);
    __nv_bfloat16* p_Bthi; cudaGetSymbolAddress((void**)&p_Bthi, g_Bthi);
    __nv_bfloat16* p_Btlo; cudaGetSymbolAddress((void**)&p_Btlo, g_Btlo);

    cudaFuncSetAttribute(gemm_mma_kernel, cudaFuncAttributeMaxDynamicSharedMemorySize, GEMM_SMEM);

    const int TB = 256;
    dim3 gemmGrid(MPAD / 128, 4);           // y covers N=512 (self 0-255 | supp 256-511)
    int convAblocks = (MPAD * 64) / 256;

    // CSR build
    zero_kernel<<<(NN + TB - 1) / TB, TB>>>(p_cursor, p_colsum, p_red, NN);
    hist_kernel<<<(EE + TB - 1) / TB, TB>>>(edge_row, p_cursor, EE);
    scan_kernel<<<1, 1024>>>(p_cursor, p_rowptr, NN);
    copy_cursor_kernel<<<(NN + TB - 1) / TB, TB>>>(p_rowptr, p_cursor, NN);
    scatter_kernel<<<(EE + TB - 1) / TB, TB>>>(edge_row, edge_col, edge_val,
                                               p_cursor, p_cols, p_vals, EE);

    // Weight transpose + bf16 split (both layers)
    convertB_kernel<<<1024, TB>>>(W_self1, W_nb1, W_self2, W_nb2, p_Bthi, p_Btlo);

    // Layer 1: fused self+nb GEMM on tensor cores (mma.sync, double-buffered)
    convertA_kernel<<<convAblocks, TB>>>(inputs, nullptr, p_Ahi, p_Alo, NN);
    gemm_mma_kernel<<<gemmGrid, TB, GEMM_SMEM>>>(p_Ahi, p_Alo, p_Bthi, p_Btlo,
                                                 p_self, p_support, NN);
    // agg1 with fused gate logits
    agg1_kernel<<<NN, 128>>>(p_self, p_support, p_rowptr, p_cols, p_vals, b1,
                             gate1_w, gate1_b, gate2_w, gate2_b,
                             p_x, p_l1, p_l2);

    // Softmax over nodes -> r, z
    reduce_max_kernel<<<1, 1024>>>(p_l1, p_l2, p_red, NN);
    reduce_sumexp_kernel<<<1, 1024>>>(p_l1, p_l2, p_red, NN);
    rz_kernel<<<(NN + TB - 1) / TB, TB>>>(p_l1, p_l2, p_red, p_r, p_z, NN);

    // Layer 2 (row-scale r fused into A conversion)
    convertA_kernel<<<convAblocks, TB>>>(p_x, p_r, p_Ahi, p_Alo, NN);
    gemm_mma_kernel<<<gemmGrid, TB, GEMM_SMEM>>>(p_Ahi, p_Alo,
                                                 p_Bthi + 512 * 256, p_Btlo + 512 * 256,
                                                 p_self, p_support, NN);
    agg2_kernel<<<NN, 128>>>(p_self, p_support, p_rowptr, p_cols, p_vals, b2,
                             p_x, p_z, xenc);

    // mean over nodes -> e2p
    colsum_kernel<<<(NN + 63) / 64, TB>>>(xenc, p_colsum, NN);
    final_kernel<<<1, NOUT>>>(p_colsum, e2p_w, e2p_b, out);
}

// round 15
// speedup vs baseline: 2.8793x; 1.0644x over previous
#include <cuda_runtime.h>
#include <cuda_bf16.h>
#include <cstdint>
#include <cstddef>

// Problem constants
#define NN   100000
#define EE   3200000
#define FF   256        // NFEAT == NHID
#define NOUT 128
#define MPAD 100096     // 782 * 128

// ---------------------------------------------------------------------------
// Scratch (static __device__ globals; no allocation anywhere)
// ---------------------------------------------------------------------------
__device__ int   g_cursor[NN];
__device__ int   g_rowptr[NN + 1];
__device__ int   g_cols[EE];
__device__ float g_vals[EE];
__device__ float g_self[(size_t)NN * FF];      // x @ W_self
__device__ float g_support[(size_t)NN * FF];   // x @ W_nb
__device__ float g_x[(size_t)NN * FF];         // layer-1 output
__device__ float g_l1[NN], g_l2[NN];
__device__ float g_r[NN], g_z[NN];
__device__ float g_red[4];
__device__ float g_colsum[FF];
// bf16-split operands
__device__ __nv_bfloat16 g_Ahi[(size_t)MPAD * FF];
__device__ __nv_bfloat16 g_Alo[(size_t)MPAD * FF];
__device__ __nv_bfloat16 g_Bthi[2 * 512 * 256];   // [layer][n][k], n = [self | nb]
__device__ __nv_bfloat16 g_Btlo[2 * 512 * 256];

// ---------------------------------------------------------------------------
// mma.sync / ldmatrix / cp.async helpers (baseline PTX, no 'a'-suffix features)
// ---------------------------------------------------------------------------
__device__ __forceinline__ void ldsm4(uint32_t* r, uint32_t addr) {
    asm volatile("ldmatrix.sync.aligned.m8n8.x4.shared.b16 {%0,%1,%2,%3}, [%4];"
        : "=r"(r[0]), "=r"(r[1]), "=r"(r[2]), "=r"(r[3]) : "r"(addr));
}

__device__ __forceinline__ void mma16816(float* c, const uint32_t* a, const uint32_t* b) {
    asm volatile("mma.sync.aligned.m16n8k16.row.col.f32.bf16.bf16.f32 "
        "{%0,%1,%2,%3}, {%4,%5,%6,%7}, {%8,%9}, {%0,%1,%2,%3};"
        : "+f"(c[0]), "+f"(c[1]), "+f"(c[2]), "+f"(c[3])
        : "r"(a[0]), "r"(a[1]), "r"(a[2]), "r"(a[3]), "r"(b[0]), "r"(b[1]));
}

__device__ __forceinline__ void cpasync16(uint32_t saddr, const void* gaddr) {
    asm volatile("cp.async.cg.shared.global [%0], [%1], 16;"
        :: "r"(saddr), "l"(gaddr) : "memory");
}
#define CP_COMMIT() asm volatile("cp.async.commit_group;" ::: "memory")
#define CP_WAIT(n)  asm volatile("cp.async.wait_group %0;" :: "n"(n) : "memory")

// ---------------------------------------------------------------------------
// CSR construction
// ---------------------------------------------------------------------------
__global__ void zero_kernel(int* cursor, float* colsum, float* red, int n)
{
    int i = blockIdx.x * blockDim.x + threadIdx.x;
    if (i < n)   cursor[i] = 0;
    if (i < FF)  colsum[i] = 0.f;
    if (i < 4)   red[i] = 0.f;
}

__global__ void hist_kernel(const int* __restrict__ edge_row, int* __restrict__ cnt, int e)
{
    int i = blockIdx.x * blockDim.x + threadIdx.x;
    if (i < e) atomicAdd(&cnt[edge_row[i]], 1);
}

__global__ void scan_kernel(const int* __restrict__ cnt, int* __restrict__ rowptr, int n)
{
    __shared__ int warpsums[32];
    __shared__ int carry_s;
    int tid = threadIdx.x;
    int lane = tid & 31, w = tid >> 5;
    if (tid == 0) carry_s = 0;
    __syncthreads();
    for (int base = 0; base < n; base += 1024) {
        int i = base + tid;
        int v = (i < n) ? cnt[i] : 0;
        int incl = v;
        #pragma unroll
        for (int o = 1; o < 32; o <<= 1) {
            int t = __shfl_up_sync(0xFFFFFFFFu, incl, o);
            if (lane >= o) incl += t;
        }
        if (lane == 31) warpsums[w] = incl;
        __syncthreads();
        if (w == 0) {
            int s = warpsums[lane];
            #pragma unroll
            for (int o = 1; o < 32; o <<= 1) {
                int t = __shfl_up_sync(0xFFFFFFFFu, s, o);
                if (lane >= o) s += t;
            }
            warpsums[lane] = s;
        }
        __syncthreads();
        int blockIncl = incl + (w > 0 ? warpsums[w - 1] : 0);
        int carry = carry_s;
        if (i < n) rowptr[i] = carry + blockIncl - v;
        __syncthreads();
        if (tid == 1023) carry_s = carry + blockIncl;
        __syncthreads();
    }
    if (tid == 0) rowptr[n] = carry_s;
}

__global__ void copy_cursor_kernel(const int* __restrict__ rowptr, int* __restrict__ cursor, int n)
{
    int i = blockIdx.x * blockDim.x + threadIdx.x;
    if (i < n) cursor[i] = rowptr[i];
}

__global__ void scatter_kernel(const int* __restrict__ edge_row,
                               const int* __restrict__ edge_col,
                               const float* __restrict__ edge_val,
                               int* __restrict__ cursor,
                               int* __restrict__ cols, float* __restrict__ vals, int e)
{
    int i = blockIdx.x * blockDim.x + threadIdx.x;
    if (i < e) {
        int r = edge_row[i];
        int p = atomicAdd(&cursor[r], 1);
        cols[p] = edge_col[i];
        vals[p] = edge_val[i];
    }
}

// ---------------------------------------------------------------------------
// bf16-split conversions
// ---------------------------------------------------------------------------
__global__ void convertA_kernel(const float* __restrict__ src,
                                __nv_bfloat16* __restrict__ hi, __nv_bfloat16* __restrict__ lo, int M)
{
    size_t idx = (size_t)blockIdx.x * 256 + threadIdx.x;   // one float4 group (4 elems)
    int row = (int)(idx >> 6);                             // 64 groups per 256-wide row
    if (row >= MPAD) return;
    float4 v = make_float4(0.f, 0.f, 0.f, 0.f);
    if (row < M) v = *(const float4*)(src + idx * 4);
    __nv_bfloat16 h0 = __float2bfloat16(v.x), h1 = __float2bfloat16(v.y);
    __nv_bfloat16 h2 = __float2bfloat16(v.z), h3 = __float2bfloat16(v.w);
    __nv_bfloat16 l0 = __float2bfloat16(v.x - __bfloat162float(h0));
    __nv_bfloat16 l1 = __float2bfloat16(v.y - __bfloat162float(h1));
    __nv_bfloat16 l2 = __float2bfloat16(v.z - __bfloat162float(h2));
    __nv_bfloat16 l3 = __float2bfloat16(v.w - __bfloat162float(h3));
    __nv_bfloat162* hp = (__nv_bfloat162*)(hi + idx * 4);
    __nv_bfloat162* lp = (__nv_bfloat162*)(lo + idx * 4);
    hp[0] = __halves2bfloat162(h0, h1); hp[1] = __halves2bfloat162(h2, h3);
    lp[0] = __halves2bfloat162(l0, l1); lp[1] = __halves2bfloat162(l2, l3);
}

// Transpose + split all 4 weight matrices into [layer][n 0..511][k] bf16 hi/lo
__global__ void convertB_kernel(const float* __restrict__ Ws1, const float* __restrict__ Wn1,
                                const float* __restrict__ Ws2, const float* __restrict__ Wn2,
                                __nv_bfloat16* __restrict__ hi, __nv_bfloat16* __restrict__ lo)
{
    int idx = blockIdx.x * 256 + threadIdx.x;   // layer*131072 + n*256 + k
    int layer = idx >> 17;
    int rem = idx & 131071;
    int n = rem >> 8, k = rem & 255;
    const float* W = layer ? (n < 256 ? Ws2 : Wn2) : (n < 256 ? Ws1 : Wn1);
    float v = W[k * 256 + (n & 255)];
    __nv_bfloat16 h = __float2bfloat16(v);
    hi[idx] = h;
    lo[idx] = __float2bfloat16(v - __bfloat162float(h));
}

// ---------------------------------------------------------------------------
// Tensor-core GEMM via mma.sync (bf16 3-product split, fp32 accum):
//   [outSelf | outSupp][M,256] = A[M,256] @ Bt^T   (Bt = [512][256], k-contig)
// Block tile 128x128, 8 warps (2 m x 4 n), warp tile 64x32, K chunk 32.
// 2-stage cp.async double buffer. SMEM rows 80 B pitch (conflict-free ldmatrix).
// ---------------------------------------------------------------------------
#define PITCH 80
#define PLANE_BYTES (128 * PITCH)          // 10240
#define STAGE_BYTES (4 * PLANE_BYTES)      // 40960: Ahi, Alo, Bhi, Blo
#define GEMM_SMEM   (2 * STAGE_BYTES)      // 81920

__device__ __forceinline__ void gemm_load_chunk(
    const __nv_bfloat16* __restrict__ Ahi, const __nv_bfloat16* __restrict__ Alo,
    const __nv_bfloat16* __restrict__ Bthi, const __nv_bfloat16* __restrict__ Btlo,
    uint32_t stageAddr, int rowTile, int nGlob, int kbase, int tid)
{
    #pragma unroll
    for (int rep = 0; rep < 4; rep++) {
        int i = tid + rep * 256;               // 0..1023
        int plane = i >> 9;
        int rem = i & 511;
        int row = rem >> 2;
        int q = rem & 3;
        const __nv_bfloat16* sp = plane ? Alo : Ahi;
        cpasync16(stageAddr + plane * PLANE_BYTES + row * PITCH + q * 16,
                  sp + (size_t)(rowTile + row) * 256 + kbase + q * 8);
    }
    #pragma unroll
    for (int rep = 0; rep < 4; rep++) {
        int i = tid + rep * 256;
        int plane = i >> 9;
        int rem = i & 511;
        int row = rem >> 2;
        int q = rem & 3;
        const __nv_bfloat16* sp = plane ? Btlo : Bthi;
        cpasync16(stageAddr + (2 + plane) * PLANE_BYTES + row * PITCH + q * 16,
                  sp + (size_t)(nGlob + row) * 256 + kbase + q * 8);
    }
}

__global__ void __launch_bounds__(256)
gemm_mma_kernel(const __nv_bfloat16* __restrict__ Ahi, const __nv_bfloat16* __restrict__ Alo,
                const __nv_bfloat16* __restrict__ Bthi, const __nv_bfloat16* __restrict__ Btlo,
                float* __restrict__ outSelf, float* __restrict__ outSupp, int M)
{
    extern __shared__ __align__(16) unsigned char dsm[];
    uint32_t smemBase = (uint32_t)__cvta_generic_to_shared(dsm);

    int tid = threadIdx.x, wid = tid >> 5, lane = tid & 31;
    int wm = wid >> 2, wn = wid & 3;
    int rowTile = blockIdx.x * 128;
    int nGlob = blockIdx.y * 128;
    float* out = (nGlob < 256) ? outSelf : outSupp;
    int colBase = nGlob & 255;

    float acc[4][4][4];
    #pragma unroll
    for (int mt = 0; mt < 4; mt++)
        #pragma unroll
        for (int nt = 0; nt < 4; nt++)
            #pragma unroll
            for (int q = 0; q < 4; q++) acc[mt][nt][q] = 0.f;

    uint32_t aOff = (uint32_t)((wm * 64 + (lane & 15)) * PITCH + (lane >> 4) * 16);
    uint32_t bOff = (uint32_t)((wn * 32 + ((lane >> 4) & 1) * 8 + (lane & 7)) * PITCH
                               + ((lane >> 3) & 1) * 16);

    gemm_load_chunk(Ahi, Alo, Bthi, Btlo, smemBase, rowTile, nGlob, 0, tid);
    CP_COMMIT();

    for (int c = 0; c < 8; c++) {
        if (c < 7) {
            gemm_load_chunk(Ahi, Alo, Bthi, Btlo,
                            smemBase + ((c + 1) & 1) * STAGE_BYTES,
                            rowTile, nGlob, (c + 1) * 32, tid);
            CP_COMMIT();
            CP_WAIT(1);
        } else {
            CP_WAIT(0);
        }
        __syncthreads();

        uint32_t st = smemBase + (c & 1) * STAGE_BYTES;
        uint32_t aBase0 = st;
        uint32_t aBase1 = st + PLANE_BYTES;
        uint32_t bBase0 = st + 2 * PLANE_BYTES;
        uint32_t bBase1 = st + 3 * PLANE_BYTES;

        #pragma unroll
        for (int kstep = 0; kstep < 2; kstep++) {
            uint32_t kb = kstep * 32;                 // 16 bf16 = 32 bytes
            uint32_t Af[4][4], Bh[2][4], Bl[2][4];
            #pragma unroll
            for (int mt = 0; mt < 4; mt++)
                ldsm4(Af[mt], aBase0 + aOff + mt * (16 * PITCH) + kb);
            #pragma unroll
            for (int bt = 0; bt < 2; bt++)
                ldsm4(Bh[bt], bBase0 + bOff + bt * (16 * PITCH) + kb);
            #pragma unroll
            for (int mt = 0; mt < 4; mt++)
                #pragma unroll
                for (int bt = 0; bt < 2; bt++) {
                    mma16816(acc[mt][bt * 2 + 0], Af[mt], &Bh[bt][0]);
                    mma16816(acc[mt][bt * 2 + 1], Af[mt], &Bh[bt][2]);
                }
            #pragma unroll
            for (int bt = 0; bt < 2; bt++)
                ldsm4(Bl[bt], bBase1 + bOff + bt * (16 * PITCH) + kb);
            #pragma unroll
            for (int mt = 0; mt < 4; mt++)
                #pragma unroll
                for (int bt = 0; bt < 2; bt++) {
                    mma16816(acc[mt][bt * 2 + 0], Af[mt], &Bl[bt][0]);
                    mma16816(acc[mt][bt * 2 + 1], Af[mt], &Bl[bt][2]);
                }
            #pragma unroll
            for (int mt = 0; mt < 4; mt++)
                ldsm4(Af[mt], aBase1 + aOff + mt * (16 * PITCH) + kb);
            #pragma unroll
            for (int mt = 0; mt < 4; mt++)
                #pragma unroll
                for (int bt = 0; bt < 2; bt++) {
                    mma16816(acc[mt][bt * 2 + 0], Af[mt], &Bh[bt][0]);
                    mma16816(acc[mt][bt * 2 + 1], Af[mt], &Bh[bt][2]);
                }
        }
        __syncthreads();
    }

    int rBase = rowTile + wm * 64 + (lane >> 2);
    int cBase = colBase + wn * 32 + (lane & 3) * 2;
    #pragma unroll
    for (int mt = 0; mt < 4; mt++) {
        int r0 = rBase + mt * 16;
        #pragma unroll
        for (int nt = 0; nt < 4; nt++) {
            int c = cBase + nt * 8;
            if (r0 < M)
                *(float2*)(out + (size_t)r0 * 256 + c) = make_float2(acc[mt][nt][0], acc[mt][nt][1]);
            if (r0 + 8 < M)
                *(float2*)(out + (size_t)(r0 + 8) * 256 + c) = make_float2(acc[mt][nt][2], acc[mt][nt][3]);
        }
    }
}

// ---------------------------------------------------------------------------
// Aggregation (128 threads, float2 per thread):
//   x[i] = relu(self[i] + sum_{edges of i} val * support[col] + b)
// agg1: also emits gate logits (block reduce) AND the bf16 hi/lo split of x
//       (feeds GEMM2 directly — r is hoisted out of layer 2).
// ---------------------------------------------------------------------------
__global__ void __launch_bounds__(128)
agg1_kernel(const float* __restrict__ selfbuf, const float* __restrict__ support,
            const int* __restrict__ rowptr, const int* __restrict__ cols,
            const float* __restrict__ vals, const float* __restrict__ bias,
            const float* __restrict__ w1, const float* __restrict__ b1,
            const float* __restrict__ w2, const float* __restrict__ b2,
            float* __restrict__ out,
            __nv_bfloat16* __restrict__ Ahi, __nv_bfloat16* __restrict__ Alo,
            float* __restrict__ l1, float* __restrict__ l2)
{
    int i = blockIdx.x;
    int j = threadIdx.x;               // column pair (2j, 2j+1)
    __shared__ int   sc[128];
    __shared__ float sv[128];
    __shared__ float red1[4], red2[4];
    int s = rowptr[i], e = rowptr[i + 1];
    float2 acc = *(const float2*)(selfbuf + (size_t)i * FF + j * 2);
    const float* supJ = support + j * 2;
    for (int b0 = s; b0 < e; b0 += 128) {
        int n = min(128, e - b0);
        __syncthreads();
        if (j < n) { sc[j] = cols[b0 + j]; sv[j] = vals[b0 + j]; }
        __syncthreads();
        #pragma unroll 8
        for (int t = 0; t < n; t++) {
            float2 p = *(const float2*)(supJ + (size_t)sc[t] * FF);
            acc.x = fmaf(sv[t], p.x, acc.x);
            acc.y = fmaf(sv[t], p.y, acc.y);
        }
    }
    acc.x = fmaxf(acc.x + bias[j * 2], 0.f);
    acc.y = fmaxf(acc.y + bias[j * 2 + 1], 0.f);
    *(float2*)(out + (size_t)i * FF + j * 2) = acc;

    // bf16 hi/lo split of x for layer-2 GEMM (r hoisted out of the GEMM)
    __nv_bfloat16 hx = __float2bfloat16(acc.x);
    __nv_bfloat16 hy = __float2bfloat16(acc.y);
    __nv_bfloat16 lx = __float2bfloat16(acc.x - __bfloat162float(hx));
    __nv_bfloat16 ly = __float2bfloat16(acc.y - __bfloat162float(hy));
    *(__nv_bfloat162*)(Ahi + (size_t)i * FF + j * 2) = __halves2bfloat162(hx, hy);
    *(__nv_bfloat162*)(Alo + (size_t)i * FF + j * 2) = __halves2bfloat162(lx, ly);

    // fused gate logits: dot(x_row, w1/w2) via block reduce
    float g1 = acc.x * w1[j * 2] + acc.y * w1[j * 2 + 1];
    float g2 = acc.x * w2[j * 2] + acc.y * w2[j * 2 + 1];
    #pragma unroll
    for (int o = 16; o > 0; o >>= 1) {
        g1 += __shfl_xor_sync(0xFFFFFFFFu, g1, o);
        g2 += __shfl_xor_sync(0xFFFFFFFFu, g2, o);
    }
    int lane = j & 31, w = j >> 5;
    if (lane == 0) { red1[w] = g1; red2[w] = g2; }
    __syncthreads();
    if (j == 0) {
        l1[i] = red1[0] + red1[1] + red1[2] + red1[3] + b1[0];
        l2[i] = red2[0] + red2[1] + red2[2] + red2[3] + b2[0];
    }
}

// Layer 2 with hoisted r:  x2 = relu(r[i]*selfRaw[i] + sum val*r[col]*suppRaw[col] + b)
//                          xenc = (1-z)*x + z*x2
__global__ void __launch_bounds__(128)
agg2_kernel(const float* __restrict__ selfbuf, const float* __restrict__ support,
            const int* __restrict__ rowptr, const int* __restrict__ cols,
            const float* __restrict__ vals, const float* __restrict__ bias,
            const float* __restrict__ x, const float* __restrict__ rg,
            const float* __restrict__ z, float* __restrict__ xenc)
{
    int i = blockIdx.x;
    int j = threadIdx.x;
    __shared__ int   sc[128];
    __shared__ float sv[128];
    int s = rowptr[i], e = rowptr[i + 1];
    float ri = rg[i];
    float2 selfv = *(const float2*)(selfbuf + (size_t)i * FF + j * 2);
    float2 acc = make_float2(ri * selfv.x, ri * selfv.y);
    const float* supJ = support + j * 2;
    for (int b0 = s; b0 < e; b0 += 128) {
        int n = min(128, e - b0);
        __syncthreads();
        if (j < n) {
            int c_ = cols[b0 + j];
            sc[j] = c_;
            sv[j] = vals[b0 + j] * rg[c_];     // fold r[col] into edge weight
        }
        __syncthreads();
        #pragma unroll 8
        for (int t = 0; t < n; t++) {
            float2 p = *(const float2*)(supJ + (size_t)sc[t] * FF);
            acc.x = fmaf(sv[t], p.x, acc.x);
            acc.y = fmaf(sv[t], p.y, acc.y);
        }
    }
    float x2a = fmaxf(acc.x + bias[j * 2], 0.f);
    float x2b = fmaxf(acc.y + bias[j * 2 + 1], 0.f);
    float zi = z[i];
    float2 xv = *(const float2*)(x + (size_t)i * FF + j * 2);
    float2 r;
    r.x = (1.f - zi) * xv.x + zi * x2a;
    r.y = (1.f - zi) * xv.y + zi * x2b;
    *(float2*)(xenc + (size_t)i * FF + j * 2) = r;
}

// ---------------------------------------------------------------------------
// Softmax reductions over node logits
// ---------------------------------------------------------------------------
__global__ void reduce_max_kernel(const float* __restrict__ l1, const float* __restrict__ l2,
                                  float* __restrict__ red, int n)
{
    float m1 = -3.4e38f, m2 = -3.4e38f;
    for (int i = threadIdx.x; i < n; i += blockDim.x) {
        m1 = fmaxf(m1, l1[i]); m2 = fmaxf(m2, l2[i]);
    }
    __shared__ float sh1[32], sh2[32];
    int lane = threadIdx.x & 31, w = threadIdx.x >> 5;
    #pragma unroll
    for (int o = 16; o > 0; o >>= 1) {
        m1 = fmaxf(m1, __shfl_xor_sync(0xFFFFFFFFu, m1, o));
        m2 = fmaxf(m2, __shfl_xor_sync(0xFFFFFFFFu, m2, o));
    }
    if (lane == 0) { sh1[w] = m1; sh2[w] = m2; }
    __syncthreads();
    if (w == 0) {
        m1 = (lane < (int)(blockDim.x >> 5)) ? sh1[lane] : -3.4e38f;
        m2 = (lane < (int)(blockDim.x >> 5)) ? sh2[lane] : -3.4e38f;
        #pragma unroll
        for (int o = 16; o > 0; o >>= 1) {
            m1 = fmaxf(m1, __shfl_xor_sync(0xFFFFFFFFu, m1, o));
            m2 = fmaxf(m2, __shfl_xor_sync(0xFFFFFFFFu, m2, o));
        }
        if (lane == 0) { red[0] = m1; red[1] = m2; }
    }
}

__global__ void reduce_sumexp_kernel(const float* __restrict__ l1, const float* __restrict__ l2,
                                     float* __restrict__ red, int n)
{
    float m1 = red[0], m2 = red[1];
    float s1 = 0.f, s2 = 0.f;
    for (int i = threadIdx.x; i < n; i += blockDim.x) {
        s1 += expf(l1[i] - m1);
        s2 += expf(l2[i] - m2);
    }
    __shared__ float sh1[32], sh2[32];
    int lane = threadIdx.x & 31, w = threadIdx.x >> 5;
    #pragma unroll
    for (int o = 16; o > 0; o >>= 1) {
        s1 += __shfl_xor_sync(0xFFFFFFFFu, s1, o);
        s2 += __shfl_xor_sync(0xFFFFFFFFu, s2, o);
    }
    if (lane == 0) { sh1[w] = s1; sh2[w] = s2; }
    __syncthreads();
    if (w == 0) {
        s1 = (lane < (int)(blockDim.x >> 5)) ? sh1[lane] : 0.f;
        s2 = (lane < (int)(blockDim.x >> 5)) ? sh2[lane] : 0.f;
        #pragma unroll
        for (int o = 16; o > 0; o >>= 1) {
            s1 += __shfl_xor_sync(0xFFFFFFFFu, s1, o);
            s2 += __shfl_xor_sync(0xFFFFFFFFu, s2, o);
        }
        if (lane == 0) { red[2] = s1; red[3] = s2; }
    }
}

__global__ void rz_kernel(const float* __restrict__ l1, const float* __restrict__ l2,
                          const float* __restrict__ red,
                          float* __restrict__ r, float* __restrict__ z, int n)
{
    int i = blockIdx.x * blockDim.x + threadIdx.x;
    if (i < n) {
        r[i] = expf(l1[i] - red[0]) / red[2];
        z[i] = expf(l2[i] - red[1]) / red[3];
    }
}

// ---------------------------------------------------------------------------
// Mean over nodes + final projection
// ---------------------------------------------------------------------------
__global__ void colsum_kernel(const float* __restrict__ xenc, float* __restrict__ colacc, int n)
{
    int j = threadIdx.x;
    int r0 = blockIdx.x * 64;
    int r1 = min(r0 + 64, n);
    float s = 0.f;
    for (int r = r0; r < r1; r++) s += xenc[(size_t)r * FF + j];
    atomicAdd(&colacc[j], s);
}

__global__ void final_kernel(const float* __restrict__ colacc,
                             const float* __restrict__ e2p_w, const float* __restrict__ e2p_b,
                             float* __restrict__ out)
{
    int o = threadIdx.x;
    float s = 0.f;
    #pragma unroll 8
    for (int k = 0; k < FF; k++)
        s = fmaf(colacc[k] * (1.0f / (float)NN), e2p_w[(size_t)k * NOUT + o], s);
    out[o] = s + e2p_b[o];
}

// ---------------------------------------------------------------------------
// Launch (fork-join across 2 streams; capture-legal: launches + event nodes only)
// ---------------------------------------------------------------------------
extern "C" void kernel_launch(void* const* d_in, const int* in_sizes, int n_in,
                              void* d_out, int out_size)
{
    const float* inputs   = (const float*)d_in[0];
    const int*   edge_row = (const int*)  d_in[1];
    const int*   edge_col = (const int*)  d_in[2];
    const float* edge_val = (const float*)d_in[3];
    const float* W_self1  = (const float*)d_in[4];
    const float* W_nb1    = (const float*)d_in[5];
    const float* b1       = (const float*)d_in[6];
    const float* W_self2  = (const float*)d_in[7];
    const float* W_nb2    = (const float*)d_in[8];
    const float* b2       = (const float*)d_in[9];
    const float* gate1_w  = (const float*)d_in[10];
    const float* gate1_b  = (const float*)d_in[11];
    const float* gate2_w  = (const float*)d_in[12];
    const float* gate2_b  = (const float*)d_in[13];
    const float* e2p_w    = (const float*)d_in[14];
    const float* e2p_b    = (const float*)d_in[15];

    float* xenc = (float*)d_out;
    float* out  = (float*)d_out + (size_t)NN * FF;

    int*   p_cursor;  cudaGetSymbolAddress((void**)&p_cursor,  g_cursor);
    int*   p_rowptr;  cudaGetSymbolAddress((void**)&p_rowptr,  g_rowptr);
    int*   p_cols;    cudaGetSymbolAddress((void**)&p_cols,    g_cols);
    float* p_vals;    cudaGetSymbolAddress((void**)&p_vals,    g_vals);
    float* p_self;    cudaGetSymbolAddress((void**)&p_self,    g_self);
    float* p_support; cudaGetSymbolAddress((void**)&p_support, g_support);
    float* p_x;       cudaGetSymbolAddress((void**)&p_x,       g_x);
    float* p_l1;      cudaGetSymbolAddress((void**)&p_l1,      g_l1);
    float* p_l2;      cudaGetSymbolAddress((void**)&p_l2,      g_l2);
    float* p_r;       cudaGetSymbolAddress((void**)&p_r,       g_r);
    float* p_z;       cudaGetSymbolAddress((void**)&p_z,       g_z);
    float* p_red;     cudaGetSymbolAddress((void**)&p_red,     g_red);
    float* p_colsum;  cudaGetSymbolAddress((void**)&p_colsum,  g_colsum);
    __nv_bfloat16* p_Ahi;  cudaGetSymbolAddress((void**)&p_Ahi,  g_Ahi);
    __nv_bfloat16* p_Alo;  cudaGetSymbolAddress((void**)&p_Alo,  g_Alo);
    __nv_bfloat16* p_Bthi; cudaGetSymbolAddress((void**)&p_Bthi, g_Bthi);
    __nv_bfloat16* p_Btlo; cudaGetSymbolAddress((void**)&p_Btlo, g_Btlo);

    cudaFuncSetAttribute(gemm_mma_kernel, cudaFuncAttributeMaxDynamicSharedMemorySize, GEMM_SMEM);

    cudaStream_t s2;
    cudaStreamCreateWithFlags(&s2, cudaStreamNonBlocking);
    cudaEvent_t evFork1, evJoin1, evFork2, evJoin2;
    cudaEventCreateWithFlags(&evFork1, cudaEventDisableTiming);
    cudaEventCreateWithFlags(&evJoin1, cudaEventDisableTiming);
    cudaEventCreateWithFlags(&evFork2, cudaEventDisableTiming);
    cudaEventCreateWithFlags(&evJoin2, cudaEventDisableTiming);

    const int TB = 256;
    dim3 gemmGrid(MPAD / 128, 4);           // y covers N=512 (self 0-255 | supp 256-511)
    int convAblocks = (MPAD * 64) / 256;

    // ---- fork 1: CSR build on s2, overlapped with converts + GEMM1 on main ----
    cudaEventRecord(evFork1, 0);
    cudaStreamWaitEvent(s2, evFork1, 0);
    zero_kernel<<<(NN + TB - 1) / TB, TB, 0, s2>>>(p_cursor, p_colsum, p_red, NN);
    hist_kernel<<<(EE + TB - 1) / TB, TB, 0, s2>>>(edge_row, p_cursor, EE);
    scan_kernel<<<1, 1024, 0, s2>>>(p_cursor, p_rowptr, NN);
    copy_cursor_kernel<<<(NN + TB - 1) / TB, TB, 0, s2>>>(p_rowptr, p_cursor, NN);
    scatter_kernel<<<(EE + TB - 1) / TB, TB, 0, s2>>>(edge_row, edge_col, edge_val,
                                                      p_cursor, p_cols, p_vals, EE);
    cudaEventRecord(evJoin1, s2);

    // main: weight split, A split, layer-1 GEMM
    convertB_kernel<<<1024, TB>>>(W_self1, W_nb1, W_self2, W_nb2, p_Bthi, p_Btlo);
    convertA_kernel<<<convAblocks, TB>>>(inputs, p_Ahi, p_Alo, NN);
    gemm_mma_kernel<<<gemmGrid, TB, GEMM_SMEM>>>(p_Ahi, p_Alo, p_Bthi, p_Btlo,
                                                 p_self, p_support, NN);
    cudaStreamWaitEvent(0, evJoin1, 0);

    // agg1: x, gate logits, and bf16 split of x (layer-2 A operand)
    agg1_kernel<<<NN, 128>>>(p_self, p_support, p_rowptr, p_cols, p_vals, b1,
                             gate1_w, gate1_b, gate2_w, gate2_b,
                             p_x, p_Ahi, p_Alo, p_l1, p_l2);

    // ---- fork 2: softmax chain on s2, overlapped with GEMM2 on main ----
    cudaEventRecord(evFork2, 0);
    cudaStreamWaitEvent(s2, evFork2, 0);
    reduce_max_kernel<<<1, 1024, 0, s2>>>(p_l1, p_l2, p_red, NN);
    reduce_sumexp_kernel<<<1, 1024, 0, s2>>>(p_l1, p_l2, p_red, NN);
    rz_kernel<<<(NN + TB - 1) / TB, TB, 0, s2>>>(p_l1, p_l2, p_red, p_r, p_z, NN);
    cudaEventRecord(evJoin2, s2);

    // main: layer-2 GEMM on unscaled x (r hoisted out)
    gemm_mma_kernel<<<gemmGrid, TB, GEMM_SMEM>>>(p_Ahi, p_Alo,
                                                 p_Bthi + 512 * 256, p_Btlo + 512 * 256,
                                                 p_self, p_support, NN);
    cudaStreamWaitEvent(0, evJoin2, 0);

    // agg2 applies r[i] / r[col] in fp32, writes x_enc
    agg2_kernel<<<NN, 128>>>(p_self, p_support, p_rowptr, p_cols, p_vals, b2,
                             p_x, p_r, p_z, xenc);

    // mean over nodes -> e2p
    colsum_kernel<<<(NN + 63) / 64, TB>>>(xenc, p_colsum, NN);
    final_kernel<<<1, NOUT>>>(p_colsum, e2p_w, e2p_b, out);
}

// round 17
// speedup vs baseline: 3.4499x; 1.1982x over previous
#include <cuda_runtime.h>
#include <cuda_bf16.h>
#include <cstdint>
#include <cstddef>

// Problem constants
#define NN   100000
#define EE   3200000
#define FF   256        // NFEAT == NHID
#define NOUT 128
#define MPAD 100096     // 782 * 128

// ---------------------------------------------------------------------------
// Scratch (static __device__ globals; no allocation anywhere)
// ---------------------------------------------------------------------------
__device__ int   g_cursor[NN];
__device__ int   g_rowptr[NN + 1];
__device__ int   g_cols[EE];
__device__ float g_vals[EE];
__device__ float g_self[(size_t)NN * FF];      // fp32 (layer 1) / bf16 reuse (layer 2)
__device__ float g_support[(size_t)NN * FF];
__device__ float g_x[(size_t)NN * FF];         // layer-1 output
__device__ float g_l1[NN], g_l2[NN];
__device__ float g_r[NN], g_z[NN];
__device__ float g_red[4];
__device__ float g_colsum[FF];
// bf16-split operands
__device__ __nv_bfloat16 g_Ahi[(size_t)MPAD * FF];
__device__ __nv_bfloat16 g_Alo[(size_t)MPAD * FF];
__device__ __nv_bfloat16 g_Bthi[2 * 512 * 256];   // [layer][n][k], n = [self | nb]
__device__ __nv_bfloat16 g_Btlo[2 * 512 * 256];

// ---------------------------------------------------------------------------
// mma.sync / ldmatrix / cp.async helpers (baseline PTX, no 'a'-suffix features)
// ---------------------------------------------------------------------------
__device__ __forceinline__ void ldsm4(uint32_t* r, uint32_t addr) {
    asm volatile("ldmatrix.sync.aligned.m8n8.x4.shared.b16 {%0,%1,%2,%3}, [%4];"
        : "=r"(r[0]), "=r"(r[1]), "=r"(r[2]), "=r"(r[3]) : "r"(addr));
}

__device__ __forceinline__ void mma16816(float* c, const uint32_t* a, const uint32_t* b) {
    asm volatile("mma.sync.aligned.m16n8k16.row.col.f32.bf16.bf16.f32 "
        "{%0,%1,%2,%3}, {%4,%5,%6,%7}, {%8,%9}, {%0,%1,%2,%3};"
        : "+f"(c[0]), "+f"(c[1]), "+f"(c[2]), "+f"(c[3])
        : "r"(a[0]), "r"(a[1]), "r"(a[2]), "r"(a[3]), "r"(b[0]), "r"(b[1]));
}

__device__ __forceinline__ void cpasync16(uint32_t saddr, const void* gaddr) {
    asm volatile("cp.async.cg.shared.global [%0], [%1], 16;"
        :: "r"(saddr), "l"(gaddr) : "memory");
}
#define CP_COMMIT() asm volatile("cp.async.commit_group;" ::: "memory")
#define CP_WAIT(n)  asm volatile("cp.async.wait_group %0;" :: "n"(n) : "memory")

// ---------------------------------------------------------------------------
// CSR construction
// ---------------------------------------------------------------------------
__global__ void zero_kernel(int* cursor, float* colsum, float* red, int n)
{
    int i = blockIdx.x * blockDim.x + threadIdx.x;
    if (i < n)   cursor[i] = 0;
    if (i < FF)  colsum[i] = 0.f;
    if (i < 4)   red[i] = 0.f;
}

__global__ void hist_kernel(const int* __restrict__ edge_row, int* __restrict__ cnt, int e)
{
    int i = blockIdx.x * blockDim.x + threadIdx.x;
    if (i < e) atomicAdd(&cnt[edge_row[i]], 1);
}

__global__ void scan_kernel(const int* __restrict__ cnt, int* __restrict__ rowptr, int n)
{
    __shared__ int warpsums[32];
    __shared__ int carry_s;
    int tid = threadIdx.x;
    int lane = tid & 31, w = tid >> 5;
    if (tid == 0) carry_s = 0;
    __syncthreads();
    for (int base = 0; base < n; base += 1024) {
        int i = base + tid;
        int v = (i < n) ? cnt[i] : 0;
        int incl = v;
        #pragma unroll
        for (int o = 1; o < 32; o <<= 1) {
            int t = __shfl_up_sync(0xFFFFFFFFu, incl, o);
            if (lane >= o) incl += t;
        }
        if (lane == 31) warpsums[w] = incl;
        __syncthreads();
        if (w == 0) {
            int s = warpsums[lane];
            #pragma unroll
            for (int o = 1; o < 32; o <<= 1) {
                int t = __shfl_up_sync(0xFFFFFFFFu, s, o);
                if (lane >= o) s += t;
            }
            warpsums[lane] = s;
        }
        __syncthreads();
        int blockIncl = incl + (w > 0 ? warpsums[w - 1] : 0);
        int carry = carry_s;
        if (i < n) rowptr[i] = carry + blockIncl - v;
        __syncthreads();
        if (tid == 1023) carry_s = carry + blockIncl;
        __syncthreads();
    }
    if (tid == 0) rowptr[n] = carry_s;
}

__global__ void copy_cursor_kernel(const int* __restrict__ rowptr, int* __restrict__ cursor, int n)
{
    int i = blockIdx.x * blockDim.x + threadIdx.x;
    if (i < n) cursor[i] = rowptr[i];
}

__global__ void scatter_kernel(const int* __restrict__ edge_row,
                               const int* __restrict__ edge_col,
                               const float* __restrict__ edge_val,
                               int* __restrict__ cursor,
                               int* __restrict__ cols, float* __restrict__ vals, int e)
{
    int i = blockIdx.x * blockDim.x + threadIdx.x;
    if (i < e) {
        int r = edge_row[i];
        int p = atomicAdd(&cursor[r], 1);
        cols[p] = edge_col[i];
        vals[p] = edge_val[i];
    }
}

// ---------------------------------------------------------------------------
// bf16-split conversions
// ---------------------------------------------------------------------------
__global__ void convertA_kernel(const float* __restrict__ src,
                                __nv_bfloat16* __restrict__ hi, __nv_bfloat16* __restrict__ lo, int M)
{
    size_t idx = (size_t)blockIdx.x * 256 + threadIdx.x;   // one float4 group (4 elems)
    int row = (int)(idx >> 6);                             // 64 groups per 256-wide row
    if (row >= MPAD) return;
    float4 v = make_float4(0.f, 0.f, 0.f, 0.f);
    if (row < M) v = *(const float4*)(src + idx * 4);
    __nv_bfloat16 h0 = __float2bfloat16(v.x), h1 = __float2bfloat16(v.y);
    __nv_bfloat16 h2 = __float2bfloat16(v.z), h3 = __float2bfloat16(v.w);
    __nv_bfloat16 l0 = __float2bfloat16(v.x - __bfloat162float(h0));
    __nv_bfloat16 l1 = __float2bfloat16(v.y - __bfloat162float(h1));
    __nv_bfloat16 l2 = __float2bfloat16(v.z - __bfloat162float(h2));
    __nv_bfloat16 l3 = __float2bfloat16(v.w - __bfloat162float(h3));
    __nv_bfloat162* hp = (__nv_bfloat162*)(hi + idx * 4);
    __nv_bfloat162* lp = (__nv_bfloat162*)(lo + idx * 4);
    hp[0] = __halves2bfloat162(h0, h1); hp[1] = __halves2bfloat162(h2, h3);
    lp[0] = __halves2bfloat162(l0, l1); lp[1] = __halves2bfloat162(l2, l3);
}

// Transpose + split all 4 weight matrices into [layer][n 0..511][k] bf16 hi/lo
__global__ void convertB_kernel(const float* __restrict__ Ws1, const float* __restrict__ Wn1,
                                const float* __restrict__ Ws2, const float* __restrict__ Wn2,
                                __nv_bfloat16* __restrict__ hi, __nv_bfloat16* __restrict__ lo)
{
    int idx = blockIdx.x * 256 + threadIdx.x;   // layer*131072 + n*256 + k
    int layer = idx >> 17;
    int rem = idx & 131071;
    int n = rem >> 8, k = rem & 255;
    const float* W = layer ? (n < 256 ? Ws2 : Wn2) : (n < 256 ? Ws1 : Wn1);
    float v = W[k * 256 + (n & 255)];
    __nv_bfloat16 h = __float2bfloat16(v);
    hi[idx] = h;
    lo[idx] = __float2bfloat16(v - __bfloat162float(h));
}

// ---------------------------------------------------------------------------
// GEMM common geometry: block tile 128x128, 8 warps (2m x 4n), K chunk 32,
// 2-stage cp.async double buffer, 80 B SMEM row pitch (conflict-free ldmatrix).
// ---------------------------------------------------------------------------
#define PITCH 80
#define PLANE_BYTES (128 * PITCH)          // 10240
#define STAGE_BYTES (4 * PLANE_BYTES)      // 40960: Ahi, Alo, Bhi, Blo
#define GEMM_SMEM   (2 * STAGE_BYTES)      // 81920
#define STAGE2_BYTES (2 * PLANE_BYTES)     // 20480: A, B (single plane)
#define GEMM2_SMEM  (2 * STAGE2_BYTES)     // 40960

// ---- Layer-1 GEMM: bf16 3-product split, fp32 out (full precision path) ----
__device__ __forceinline__ void gemm_load_chunk(
    const __nv_bfloat16* __restrict__ Ahi, const __nv_bfloat16* __restrict__ Alo,
    const __nv_bfloat16* __restrict__ Bthi, const __nv_bfloat16* __restrict__ Btlo,
    uint32_t stageAddr, int rowTile, int nGlob, int kbase, int tid)
{
    #pragma unroll
    for (int rep = 0; rep < 4; rep++) {
        int i = tid + rep * 256;               // 0..1023
        int plane = i >> 9;
        int rem = i & 511;
        int row = rem >> 2;
        int q = rem & 3;
        const __nv_bfloat16* sp = plane ? Alo : Ahi;
        cpasync16(stageAddr + plane * PLANE_BYTES + row * PITCH + q * 16,
                  sp + (size_t)(rowTile + row) * 256 + kbase + q * 8);
    }
    #pragma unroll
    for (int rep = 0; rep < 4; rep++) {
        int i = tid + rep * 256;
        int plane = i >> 9;
        int rem = i & 511;
        int row = rem >> 2;
        int q = rem & 3;
        const __nv_bfloat16* sp = plane ? Btlo : Bthi;
        cpasync16(stageAddr + (2 + plane) * PLANE_BYTES + row * PITCH + q * 16,
                  sp + (size_t)(nGlob + row) * 256 + kbase + q * 8);
    }
}

__global__ void __launch_bounds__(256)
gemm_mma_kernel(const __nv_bfloat16* __restrict__ Ahi, const __nv_bfloat16* __restrict__ Alo,
                const __nv_bfloat16* __restrict__ Bthi, const __nv_bfloat16* __restrict__ Btlo,
                float* __restrict__ outSelf, float* __restrict__ outSupp, int M)
{
    extern __shared__ __align__(16) unsigned char dsm[];
    uint32_t smemBase = (uint32_t)__cvta_generic_to_shared(dsm);

    int tid = threadIdx.x, wid = tid >> 5, lane = tid & 31;
    int wm = wid >> 2, wn = wid & 3;
    int rowTile = blockIdx.x * 128;
    int nGlob = blockIdx.y * 128;
    float* out = (nGlob < 256) ? outSelf : outSupp;
    int colBase = nGlob & 255;

    float acc[4][4][4];
    #pragma unroll
    for (int mt = 0; mt < 4; mt++)
        #pragma unroll
        for (int nt = 0; nt < 4; nt++)
            #pragma unroll
            for (int q = 0; q < 4; q++) acc[mt][nt][q] = 0.f;

    uint32_t aOff = (uint32_t)((wm * 64 + (lane & 15)) * PITCH + (lane >> 4) * 16);
    uint32_t bOff = (uint32_t)((wn * 32 + ((lane >> 4) & 1) * 8 + (lane & 7)) * PITCH
                               + ((lane >> 3) & 1) * 16);

    gemm_load_chunk(Ahi, Alo, Bthi, Btlo, smemBase, rowTile, nGlob, 0, tid);
    CP_COMMIT();

    for (int c = 0; c < 8; c++) {
        if (c < 7) {
            gemm_load_chunk(Ahi, Alo, Bthi, Btlo,
                            smemBase + ((c + 1) & 1) * STAGE_BYTES,
                            rowTile, nGlob, (c + 1) * 32, tid);
            CP_COMMIT();
            CP_WAIT(1);
        } else {
            CP_WAIT(0);
        }
        __syncthreads();

        uint32_t st = smemBase + (c & 1) * STAGE_BYTES;
        uint32_t aBase0 = st;
        uint32_t aBase1 = st + PLANE_BYTES;
        uint32_t bBase0 = st + 2 * PLANE_BYTES;
        uint32_t bBase1 = st + 3 * PLANE_BYTES;

        #pragma unroll
        for (int kstep = 0; kstep < 2; kstep++) {
            uint32_t kb = kstep * 32;
            uint32_t Af[4][4], Bh[2][4], Bl[2][4];
            #pragma unroll
            for (int mt = 0; mt < 4; mt++)
                ldsm4(Af[mt], aBase0 + aOff + mt * (16 * PITCH) + kb);
            #pragma unroll
            for (int bt = 0; bt < 2; bt++)
                ldsm4(Bh[bt], bBase0 + bOff + bt * (16 * PITCH) + kb);
            #pragma unroll
            for (int mt = 0; mt < 4; mt++)
                #pragma unroll
                for (int bt = 0; bt < 2; bt++) {
                    mma16816(acc[mt][bt * 2 + 0], Af[mt], &Bh[bt][0]);
                    mma16816(acc[mt][bt * 2 + 1], Af[mt], &Bh[bt][2]);
                }
            #pragma unroll
            for (int bt = 0; bt < 2; bt++)
                ldsm4(Bl[bt], bBase1 + bOff + bt * (16 * PITCH) + kb);
            #pragma unroll
            for (int mt = 0; mt < 4; mt++)
                #pragma unroll
                for (int bt = 0; bt < 2; bt++) {
                    mma16816(acc[mt][bt * 2 + 0], Af[mt], &Bl[bt][0]);
                    mma16816(acc[mt][bt * 2 + 1], Af[mt], &Bl[bt][2]);
                }
            #pragma unroll
            for (int mt = 0; mt < 4; mt++)
                ldsm4(Af[mt], aBase1 + aOff + mt * (16 * PITCH) + kb);
            #pragma unroll
            for (int mt = 0; mt < 4; mt++)
                #pragma unroll
                for (int bt = 0; bt < 2; bt++) {
                    mma16816(acc[mt][bt * 2 + 0], Af[mt], &Bh[bt][0]);
                    mma16816(acc[mt][bt * 2 + 1], Af[mt], &Bh[bt][2]);
                }
        }
        __syncthreads();
    }

    int rBase = rowTile + wm * 64 + (lane >> 2);
    int cBase = colBase + wn * 32 + (lane & 3) * 2;
    #pragma unroll
    for (int mt = 0; mt < 4; mt++) {
        int r0 = rBase + mt * 16;
        #pragma unroll
        for (int nt = 0; nt < 4; nt++) {
            int c = cBase + nt * 8;
            if (r0 < M)
                *(float2*)(out + (size_t)r0 * 256 + c) = make_float2(acc[mt][nt][0], acc[mt][nt][1]);
            if (r0 + 8 < M)
                *(float2*)(out + (size_t)(r0 + 8) * 256 + c) = make_float2(acc[mt][nt][2], acc[mt][nt][3]);
        }
    }
}

// ---- Layer-2 GEMM: plain bf16 single product, bf16 out (z ~ 1e-5 suppresses error) ----
__global__ void __launch_bounds__(256)
gemm_bf16_kernel(const __nv_bfloat16* __restrict__ A,
                 const __nv_bfloat16* __restrict__ Bt,
                 __nv_bfloat16* __restrict__ outSelf, __nv_bfloat16* __restrict__ outSupp, int M)
{
    extern __shared__ __align__(16) unsigned char dsm[];
    uint32_t smemBase = (uint32_t)__cvta_generic_to_shared(dsm);

    int tid = threadIdx.x, wid = tid >> 5, lane = tid & 31;
    int wm = wid >> 2, wn = wid & 3;
    int rowTile = blockIdx.x * 128;
    int nGlob = blockIdx.y * 128;
    __nv_bfloat16* out = (nGlob < 256) ? outSelf : outSupp;
    int colBase = nGlob & 255;

    float acc[4][4][4];
    #pragma unroll
    for (int mt = 0; mt < 4; mt++)
        #pragma unroll
        for (int nt = 0; nt < 4; nt++)
            #pragma unroll
            for (int q = 0; q < 4; q++) acc[mt][nt][q] = 0.f;

    uint32_t aOff = (uint32_t)((wm * 64 + (lane & 15)) * PITCH + (lane >> 4) * 16);
    uint32_t bOff = (uint32_t)((wn * 32 + ((lane >> 4) & 1) * 8 + (lane & 7)) * PITCH
                               + ((lane >> 3) & 1) * 16);

    // prologue load chunk 0
    #pragma unroll
    for (int rep = 0; rep < 2; rep++) {
        int i = tid + rep * 256;       // 0..511
        int row = i >> 2, q = i & 3;
        cpasync16(smemBase + row * PITCH + q * 16,
                  A + (size_t)(rowTile + row) * 256 + q * 8);
    }
    #pragma unroll
    for (int rep = 0; rep < 2; rep++) {
        int i = tid + rep * 256;
        int row = i >> 2, q = i & 3;
        cpasync16(smemBase + PLANE_BYTES + row * PITCH + q * 16,
                  Bt + (size_t)(nGlob + row) * 256 + q * 8);
    }
    CP_COMMIT();

    for (int c = 0; c < 8; c++) {
        if (c < 7) {
            uint32_t st = smemBase + ((c + 1) & 1) * STAGE2_BYTES;
            int kb = (c + 1) * 32;
            #pragma unroll
            for (int rep = 0; rep < 2; rep++) {
                int i = tid + rep * 256;
                int row = i >> 2, q = i & 3;
                cpasync16(st + row * PITCH + q * 16,
                          A + (size_t)(rowTile + row) * 256 + kb + q * 8);
            }
            #pragma unroll
            for (int rep = 0; rep < 2; rep++) {
                int i = tid + rep * 256;
                int row = i >> 2, q = i & 3;
                cpasync16(st + PLANE_BYTES + row * PITCH + q * 16,
                          Bt + (size_t)(nGlob + row) * 256 + kb + q * 8);
            }
            CP_COMMIT();
            CP_WAIT(1);
        } else {
            CP_WAIT(0);
        }
        __syncthreads();

        uint32_t st = smemBase + (c & 1) * STAGE2_BYTES;
        #pragma unroll
        for (int kstep = 0; kstep < 2; kstep++) {
            uint32_t kb = kstep * 32;
            uint32_t Af[4][4], Bf[2][4];
            #pragma unroll
            for (int mt = 0; mt < 4; mt++)
                ldsm4(Af[mt], st + aOff + mt * (16 * PITCH) + kb);
            #pragma unroll
            for (int bt = 0; bt < 2; bt++)
                ldsm4(Bf[bt], st + PLANE_BYTES + bOff + bt * (16 * PITCH) + kb);
            #pragma unroll
            for (int mt = 0; mt < 4; mt++)
                #pragma unroll
                for (int bt = 0; bt < 2; bt++) {
                    mma16816(acc[mt][bt * 2 + 0], Af[mt], &Bf[bt][0]);
                    mma16816(acc[mt][bt * 2 + 1], Af[mt], &Bf[bt][2]);
                }
        }
        __syncthreads();
    }

    int rBase = rowTile + wm * 64 + (lane >> 2);
    int cBase = colBase + wn * 32 + (lane & 3) * 2;
    #pragma unroll
    for (int mt = 0; mt < 4; mt++) {
        int r0 = rBase + mt * 16;
        #pragma unroll
        for (int nt = 0; nt < 4; nt++) {
            int c = cBase + nt * 8;
            if (r0 < M)
                *(__nv_bfloat162*)(out + (size_t)r0 * 256 + c) =
                    __floats2bfloat162_rn(acc[mt][nt][0], acc[mt][nt][1]);
            if (r0 + 8 < M)
                *(__nv_bfloat162*)(out + (size_t)(r0 + 8) * 256 + c) =
                    __floats2bfloat162_rn(acc[mt][nt][2], acc[mt][nt][3]);
        }
    }
}

// ---------------------------------------------------------------------------
// Aggregation (128 threads, float2 per thread):
//   x[i] = relu(self[i] + sum_{edges of i} val * support[col] + b)
// agg1: fp32 gather; also emits gate logits + bf16 x (layer-2 A operand).
// ---------------------------------------------------------------------------
__global__ void __launch_bounds__(128)
agg1_kernel(const float* __restrict__ selfbuf, const float* __restrict__ support,
            const int* __restrict__ rowptr, const int* __restrict__ cols,
            const float* __restrict__ vals, const float* __restrict__ bias,
            const float* __restrict__ w1, const float* __restrict__ b1,
            const float* __restrict__ w2, const float* __restrict__ b2,
            float* __restrict__ out,
            __nv_bfloat16* __restrict__ Ahi,
            float* __restrict__ l1, float* __restrict__ l2)
{
    int i = blockIdx.x;
    int j = threadIdx.x;               // column pair (2j, 2j+1)
    __shared__ int   sc[128];
    __shared__ float sv[128];
    __shared__ float red1[4], red2[4];
    int s = rowptr[i], e = rowptr[i + 1];
    float2 acc = *(const float2*)(selfbuf + (size_t)i * FF + j * 2);
    const float* supJ = support + j * 2;
    for (int b0 = s; b0 < e; b0 += 128) {
        int n = min(128, e - b0);
        __syncthreads();
        if (j < n) { sc[j] = cols[b0 + j]; sv[j] = vals[b0 + j]; }
        __syncthreads();
        #pragma unroll 8
        for (int t = 0; t < n; t++) {
            float2 p = *(const float2*)(supJ + (size_t)sc[t] * FF);
            acc.x = fmaf(sv[t], p.x, acc.x);
            acc.y = fmaf(sv[t], p.y, acc.y);
        }
    }
    acc.x = fmaxf(acc.x + bias[j * 2], 0.f);
    acc.y = fmaxf(acc.y + bias[j * 2 + 1], 0.f);
    *(float2*)(out + (size_t)i * FF + j * 2) = acc;

    // bf16 x for layer-2 GEMM (single-product precision is enough: z ~ 1e-5)
    *(__nv_bfloat162*)(Ahi + (size_t)i * FF + j * 2) = __floats2bfloat162_rn(acc.x, acc.y);

    // fused gate logits: dot(x_row, w1/w2) via block reduce
    float g1 = acc.x * w1[j * 2] + acc.y * w1[j * 2 + 1];
    float g2 = acc.x * w2[j * 2] + acc.y * w2[j * 2 + 1];
    #pragma unroll
    for (int o = 16; o > 0; o >>= 1) {
        g1 += __shfl_xor_sync(0xFFFFFFFFu, g1, o);
        g2 += __shfl_xor_sync(0xFFFFFFFFu, g2, o);
    }
    int lane = j & 31, w = j >> 5;
    if (lane == 0) { red1[w] = g1; red2[w] = g2; }
    __syncthreads();
    if (j == 0) {
        l1[i] = red1[0] + red1[1] + red1[2] + red1[3] + b1[0];
        l2[i] = red2[0] + red2[1] + red2[2] + red2[3] + b2[0];
    }
}

// Layer 2 (bf16 gather, hoisted r):
//   x2 = relu(r[i]*selfRaw[i] + sum val*r[col]*suppRaw[col] + b)
//   xenc = (1-z)*x + z*x2
__global__ void __launch_bounds__(128)
agg2_kernel(const __nv_bfloat16* __restrict__ selfbuf, const __nv_bfloat16* __restrict__ support,
            const int* __restrict__ rowptr, const int* __restrict__ cols,
            const float* __restrict__ vals, const float* __restrict__ bias,
            const float* __restrict__ x, const float* __restrict__ rg,
            const float* __restrict__ z, float* __restrict__ xenc)
{
    int i = blockIdx.x;
    int j = threadIdx.x;
    __shared__ int   sc[128];
    __shared__ float sv[128];
    int s = rowptr[i], e = rowptr[i + 1];
    float ri = rg[i];
    float2 selfv = __bfloat1622float2(*(const __nv_bfloat162*)(selfbuf + (size_t)i * FF + j * 2));
    float2 acc = make_float2(ri * selfv.x, ri * selfv.y);
    const __nv_bfloat16* supJ = support + j * 2;
    for (int b0 = s; b0 < e; b0 += 128) {
        int n = min(128, e - b0);
        __syncthreads();
        if (j < n) {
            int c_ = cols[b0 + j];
            sc[j] = c_;
            sv[j] = vals[b0 + j] * rg[c_];     // fold r[col] into edge weight
        }
        __syncthreads();
        #pragma unroll 8
        for (int t = 0; t < n; t++) {
            float2 p = __bfloat1622float2(*(const __nv_bfloat162*)(supJ + (size_t)sc[t] * FF));
            acc.x = fmaf(sv[t], p.x, acc.x);
            acc.y = fmaf(sv[t], p.y, acc.y);
        }
    }
    float x2a = fmaxf(acc.x + bias[j * 2], 0.f);
    float x2b = fmaxf(acc.y + bias[j * 2 + 1], 0.f);
    float zi = z[i];
    float2 xv = *(const float2*)(x + (size_t)i * FF + j * 2);
    float2 r;
    r.x = (1.f - zi) * xv.x + zi * x2a;
    r.y = (1.f - zi) * xv.y + zi * x2b;
    *(float2*)(xenc + (size_t)i * FF + j * 2) = r;
}

// ---------------------------------------------------------------------------
// Softmax reductions over node logits
// ---------------------------------------------------------------------------
__global__ void reduce_max_kernel(const float* __restrict__ l1, const float* __restrict__ l2,
                                  float* __restrict__ red, int n)
{
    float m1 = -3.4e38f, m2 = -3.4e38f;
    for (int i = threadIdx.x; i < n; i += blockDim.x) {
        m1 = fmaxf(m1, l1[i]); m2 = fmaxf(m2, l2[i]);
    }
    __shared__ float sh1[32], sh2[32];
    int lane = threadIdx.x & 31, w = threadIdx.x >> 5;
    #pragma unroll
    for (int o = 16; o > 0; o >>= 1) {
        m1 = fmaxf(m1, __shfl_xor_sync(0xFFFFFFFFu, m1, o));
        m2 = fmaxf(m2, __shfl_xor_sync(0xFFFFFFFFu, m2, o));
    }
    if (lane == 0) { sh1[w] = m1; sh2[w] = m2; }
    __syncthreads();
    if (w == 0) {
        m1 = (lane < (int)(blockDim.x >> 5)) ? sh1[lane] : -3.4e38f;
        m2 = (lane < (int)(blockDim.x >> 5)) ? sh2[lane] : -3.4e38f;
        #pragma unroll
        for (int o = 16; o > 0; o >>= 1) {
            m1 = fmaxf(m1, __shfl_xor_sync(0xFFFFFFFFu, m1, o));
            m2 = fmaxf(m2, __shfl_xor_sync(0xFFFFFFFFu, m2, o));
        }
        if (lane == 0) { red[0] = m1; red[1] = m2; }
    }
}

__global__ void reduce_sumexp_kernel(const float* __restrict__ l1, const float* __restrict__ l2,
                                     float* __restrict__ red, int n)
{
    float m1 = red[0], m2 = red[1];
    float s1 = 0.f, s2 = 0.f;
    for (int i = threadIdx.x; i < n; i += blockDim.x) {
        s1 += expf(l1[i] - m1);
        s2 += expf(l2[i] - m2);
    }
    __shared__ float sh1[32], sh2[32];
    int lane = threadIdx.x & 31, w = threadIdx.x >> 5;
    #pragma unroll
    for (int o = 16; o > 0; o >>= 1) {
        s1 += __shfl_xor_sync(0xFFFFFFFFu, s1, o);
        s2 += __shfl_xor_sync(0xFFFFFFFFu, s2, o);
    }
    if (lane == 0) { sh1[w] = s1; sh2[w] = s2; }
    __syncthreads();
    if (w == 0) {
        s1 = (lane < (int)(blockDim.x >> 5)) ? sh1[lane] : 0.f;
        s2 = (lane < (int)(blockDim.x >> 5)) ? sh2[lane] : 0.f;
        #pragma unroll
        for (int o = 16; o > 0; o >>= 1) {
            s1 += __shfl_xor_sync(0xFFFFFFFFu, s1, o);
            s2 += __shfl_xor_sync(0xFFFFFFFFu, s2, o);
        }
        if (lane == 0) { red[2] = s1; red[3] = s2; }
    }
}

__global__ void rz_kernel(const float* __restrict__ l1, const float* __restrict__ l2,
                          const float* __restrict__ red,
                          float* __restrict__ r, float* __restrict__ z, int n)
{
    int i = blockIdx.x * blockDim.x + threadIdx.x;
    if (i < n) {
        r[i] = expf(l1[i] - red[0]) / red[2];
        z[i] = expf(l2[i] - red[1]) / red[3];
    }
}

// ---------------------------------------------------------------------------
// Mean over nodes + final projection
// ---------------------------------------------------------------------------
__global__ void colsum_kernel(const float* __restrict__ xenc, float* __restrict__ colacc, int n)
{
    int j = threadIdx.x;
    int r0 = blockIdx.x * 64;
    int r1 = min(r0 + 64, n);
    float s = 0.f;
    for (int r = r0; r < r1; r++) s += xenc[(size_t)r * FF + j];
    atomicAdd(&colacc[j], s);
}

__global__ void final_kernel(const float* __restrict__ colacc,
                             const float* __restrict__ e2p_w, const float* __restrict__ e2p_b,
                             float* __restrict__ out)
{
    int o = threadIdx.x;
    float s = 0.f;
    #pragma unroll 8
    for (int k = 0; k < FF; k++)
        s = fmaf(colacc[k] * (1.0f / (float)NN), e2p_w[(size_t)k * NOUT + o], s);
    out[o] = s + e2p_b[o];
}

// ---------------------------------------------------------------------------
// Launch (fork-join across 2 streams; capture-legal)
// ---------------------------------------------------------------------------
extern "C" void kernel_launch(void* const* d_in, const int* in_sizes, int n_in,
                              void* d_out, int out_size)
{
    const float* inputs   = (const float*)d_in[0];
    const int*   edge_row = (const int*)  d_in[1];
    const int*   edge_col = (const int*)  d_in[2];
    const float* edge_val = (const float*)d_in[3];
    const float* W_self1  = (const float*)d_in[4];
    const float* W_nb1    = (const float*)d_in[5];
    const float* b1       = (const float*)d_in[6];
    const float* W_self2  = (const float*)d_in[7];
    const float* W_nb2    = (const float*)d_in[8];
    const float* b2       = (const float*)d_in[9];
    const float* gate1_w  = (const float*)d_in[10];
    const float* gate1_b  = (const float*)d_in[11];
    const float* gate2_w  = (const float*)d_in[12];
    const float* gate2_b  = (const float*)d_in[13];
    const float* e2p_w    = (const float*)d_in[14];
    const float* e2p_b    = (const float*)d_in[15];

    float* xenc = (float*)d_out;
    float* out  = (float*)d_out + (size_t)NN * FF;

    int*   p_cursor;  cudaGetSymbolAddress((void**)&p_cursor,  g_cursor);
    int*   p_rowptr;  cudaGetSymbolAddress((void**)&p_rowptr,  g_rowptr);
    int*   p_cols;    cudaGetSymbolAddress((void**)&p_cols,    g_cols);
    float* p_vals;    cudaGetSymbolAddress((void**)&p_vals,    g_vals);
    float* p_self;    cudaGetSymbolAddress((void**)&p_self,    g_self);
    float* p_support; cudaGetSymbolAddress((void**)&p_support, g_support);
    float* p_x;       cudaGetSymbolAddress((void**)&p_x,       g_x);
    float* p_l1;      cudaGetSymbolAddress((void**)&p_l1,      g_l1);
    float* p_l2;      cudaGetSymbolAddress((void**)&p_l2,      g_l2);
    float* p_r;       cudaGetSymbolAddress((void**)&p_r,       g_r);
    float* p_z;       cudaGetSymbolAddress((void**)&p_z,       g_z);
    float* p_red;     cudaGetSymbolAddress((void**)&p_red,     g_red);
    float* p_colsum;  cudaGetSymbolAddress((void**)&p_colsum,  g_colsum);
    __nv_bfloat16* p_Ahi;  cudaGetSymbolAddress((void**)&p_Ahi,  g_Ahi);
    __nv_bfloat16* p_Alo;  cudaGetSymbolAddress((void**)&p_Alo,  g_Alo);
    __nv_bfloat16* p_Bthi; cudaGetSymbolAddress((void**)&p_Bthi, g_Bthi);
    __nv_bfloat16* p_Btlo; cudaGetSymbolAddress((void**)&p_Btlo, g_Btlo);

    cudaFuncSetAttribute(gemm_mma_kernel, cudaFuncAttributeMaxDynamicSharedMemorySize, GEMM_SMEM);
    cudaFuncSetAttribute(gemm_bf16_kernel, cudaFuncAttributeMaxDynamicSharedMemorySize, GEMM2_SMEM);

    cudaStream_t s2;
    cudaStreamCreateWithFlags(&s2, cudaStreamNonBlocking);
    cudaEvent_t evFork1, evJoin1, evFork2, evJoin2;
    cudaEventCreateWithFlags(&evFork1, cudaEventDisableTiming);
    cudaEventCreateWithFlags(&evJoin1, cudaEventDisableTiming);
    cudaEventCreateWithFlags(&evFork2, cudaEventDisableTiming);
    cudaEventCreateWithFlags(&evJoin2, cudaEventDisableTiming);

    const int TB = 256;
    dim3 gemmGrid(MPAD / 128, 4);           // y covers N=512 (self 0-255 | supp 256-511)
    int convAblocks = (MPAD * 64) / 256;

    // ---- fork 1: CSR build on s2, overlapped with converts + GEMM1 on main ----
    cudaEventRecord(evFork1, 0);
    cudaStreamWaitEvent(s2, evFork1, 0);
    zero_kernel<<<(NN + TB - 1) / TB, TB, 0, s2>>>(p_cursor, p_colsum, p_red, NN);
    hist_kernel<<<(EE + TB - 1) / TB, TB, 0, s2>>>(edge_row, p_cursor, EE);
    scan_kernel<<<1, 1024, 0, s2>>>(p_cursor, p_rowptr, NN);
    copy_cursor_kernel<<<(NN + TB - 1) / TB, TB, 0, s2>>>(p_rowptr, p_cursor, NN);
    scatter_kernel<<<(EE + TB - 1) / TB, TB, 0, s2>>>(edge_row, edge_col, edge_val,
                                                      p_cursor, p_cols, p_vals, EE);
    cudaEventRecord(evJoin1, s2);

    // main: weight split, A split, layer-1 GEMM (full split precision)
    convertB_kernel<<<1024, TB>>>(W_self1, W_nb1, W_self2, W_nb2, p_Bthi, p_Btlo);
    convertA_kernel<<<convAblocks, TB>>>(inputs, p_Ahi, p_Alo, NN);
    gemm_mma_kernel<<<gemmGrid, TB, GEMM_SMEM>>>(p_Ahi, p_Alo, p_Bthi, p_Btlo,
                                                 p_self, p_support, NN);
    cudaStreamWaitEvent(0, evJoin1, 0);

    // agg1: x, gate logits, and bf16 x (layer-2 A operand)
    agg1_kernel<<<NN, 128>>>(p_self, p_support, p_rowptr, p_cols, p_vals, b1,
                             gate1_w, gate1_b, gate2_w, gate2_b,
                             p_x, p_Ahi, p_l1, p_l2);

    // ---- fork 2: softmax chain on s2, overlapped with GEMM2 on main ----
    cudaEventRecord(evFork2, 0);
    cudaStreamWaitEvent(s2, evFork2, 0);
    reduce_max_kernel<<<1, 1024, 0, s2>>>(p_l1, p_l2, p_red, NN);
    reduce_sumexp_kernel<<<1, 1024, 0, s2>>>(p_l1, p_l2, p_red, NN);
    rz_kernel<<<(NN + TB - 1) / TB, TB, 0, s2>>>(p_l1, p_l2, p_red, p_r, p_z, NN);
    cudaEventRecord(evJoin2, s2);

    // main: layer-2 GEMM, plain bf16, bf16 outputs into reused buffers
    gemm_bf16_kernel<<<gemmGrid, TB, GEMM2_SMEM>>>(p_Ahi, p_Bthi + 512 * 256,
                                                   (__nv_bfloat16*)p_self,
                                                   (__nv_bfloat16*)p_support, NN);
    cudaStreamWaitEvent(0, evJoin2, 0);

    // agg2: bf16 gather, applies r[i]/r[col] in fp32, writes x_enc
    agg2_kernel<<<NN, 128>>>((const __nv_bfloat16*)p_self, (const __nv_bfloat16*)p_support,
                             p_rowptr, p_cols, p_vals, b2,
                             p_x, p_r, p_z, xenc);

    // mean over nodes -> e2p
    colsum_kernel<<<(NN + 63) / 64, TB>>>(xenc, p_colsum, NN);
    final_kernel<<<1, NOUT>>>(p_colsum, e2p_w, e2p_b, out);
}